// round 1
// baseline (speedup 1.0000x reference)
#include <cuda_runtime.h>
#include <stdint.h>

// ---------------------------------------------------------------------------
// EdgeFeat: n_proj gather-mul + geo linear + FiLM + relu, fused.
//
//   n_proj = node_feats @ Wn + bn                     [N,64]
//   join   = [ n_proj[src]*n_proj[dst] , e_geo@Wg+bg ][E,96]
//   x      = join @ Wx                                 [E,64]
//   out    = relu(x * (gamma[bid]+1) + beta[bid])
//
// Algebraic reduction: x = njoin @ Wx[0:64] + e_geo @ (Wg@Wx[64:96]) + bg@Wx[64:96]
// -> single K=72 GEMM against precomputed Wcomb[72,64] + cbias[64].
// ---------------------------------------------------------------------------

#define NODE_DIM 64
#define EDGE_DIM 64
#define GEO_DIM  8
#define GEO_OUT  32
#define COND_DIM 512
#define KTOT     72            // 64 (node-join) + 8 (geo, folded through Wg)
#define MAX_NODES  100000
#define MAX_EDGES  800000
#define MAX_GRAPHS 64

// Scratch (allocation-free rule: __device__ globals)
__device__ float g_nproj[MAX_NODES * NODE_DIM];          // 25.6 MB
__device__ int   g_src[MAX_EDGES];
__device__ int   g_dst[MAX_EDGES];
__device__ int   g_bid[MAX_EDGES];
__device__ float g_gamma_beta[MAX_GRAPHS * 2 * EDGE_DIM]; // [B][gamma(64)|beta(64)]
__device__ float g_wcomb[KTOT * EDGE_DIM];
__device__ float g_cbias[EDGE_DIM];
__device__ int   g_ei_is64;
__device__ int   g_bid_is64;

// ---------------------------------------------------------------------------
// Dtype probe: reference says int64 but JAX without x64 silently emits int32.
// Sampled int64 reads stay within the smaller dtype's byte footprint:
//   edge_index: >= 8E bytes under both dtypes -> sample E int64 slots
//   batch_ids : >= 4E bytes under both dtypes -> sample E/2 int64 slots
// Values < 2^17, so a nonzero high word proves int32 packing.
// ---------------------------------------------------------------------------
__global__ void detect_kernel(const void* ei, const void* bids, int E) {
    __shared__ int bad_ei, bad_bid;
    if (threadIdx.x == 0) { bad_ei = 0; bad_bid = 0; }
    __syncthreads();
    const unsigned long long* p64 = (const unsigned long long*)ei;
    const unsigned long long* b64 = (const unsigned long long*)bids;
    const int samples = 2048;
    long long n_ei = E;
    long long st_e = n_ei / samples; if (st_e < 1) st_e = 1;
    for (int i = threadIdx.x; i < samples; i += blockDim.x) {
        long long idx = (long long)i * st_e;
        if (idx >= n_ei) break;
        if (p64[idx] >> 32) bad_ei = 1;   // benign race: all writers store 1
    }
    long long n_b = E / 2;
    long long st_b = n_b / samples; if (st_b < 1) st_b = 1;
    for (int i = threadIdx.x; i < samples; i += blockDim.x) {
        long long idx = (long long)i * st_b;
        if (idx >= n_b) break;
        if (b64[idx] >> 32) bad_bid = 1;
    }
    __syncthreads();
    if (threadIdx.x == 0) { g_ei_is64 = !bad_ei; g_bid_is64 = !bad_bid; }
}

__global__ void convert_kernel(const void* ei, const void* bids, int E) {
    int e = blockIdx.x * blockDim.x + threadIdx.x;
    if (e >= E) return;
    if (g_ei_is64) {
        const long long* p = (const long long*)ei;
        g_src[e] = (int)p[e];
        g_dst[e] = (int)p[(size_t)E + e];
    } else {
        const int* p = (const int*)ei;
        g_src[e] = p[e];
        g_dst[e] = p[E + e];
    }
    if (g_bid_is64) g_bid[e] = (int)((const long long*)bids)[e];
    else            g_bid[e] = ((const int*)bids)[e];
}

// ---------------------------------------------------------------------------
// FiLM table: gamma_beta[b][j] = cond[b]@Wc[:,j] + bc[j]  (+1 for gamma half)
// ---------------------------------------------------------------------------
__global__ void film_kernel(const float* __restrict__ cond,
                            const float* __restrict__ Wc,
                            const float* __restrict__ bc) {
    int b = blockIdx.x;
    int j = threadIdx.x;                      // 128 threads
    const float* crow = cond + (size_t)b * COND_DIM;
    float acc = bc[j];
    #pragma unroll 4
    for (int k = 0; k < COND_DIM; k++)
        acc += crow[k] * Wc[(size_t)k * (2 * EDGE_DIM) + j];   // coalesced on j
    if (j < EDGE_DIM) acc += 1.0f;            // gamma + 1
    g_gamma_beta[b * (2 * EDGE_DIM) + j] = acc;
}

// ---------------------------------------------------------------------------
// Wcomb[0:64]  = Wx[0:64]
// Wcomb[64:72] = Wg @ Wx[64:96]   ;   cbias = bg @ Wx[64:96]
// ---------------------------------------------------------------------------
__global__ void wcomb_kernel(const float* __restrict__ Wg,
                             const float* __restrict__ bg,
                             const float* __restrict__ Wx) {
    for (int idx = threadIdx.x; idx < KTOT * EDGE_DIM; idx += blockDim.x) {
        int k = idx / EDGE_DIM, c = idx % EDGE_DIM;
        float v;
        if (k < EDGE_DIM) {
            v = Wx[k * EDGE_DIM + c];
        } else {
            v = 0.f;
            int gk = k - EDGE_DIM;
            #pragma unroll
            for (int m = 0; m < GEO_OUT; m++)
                v += Wg[gk * GEO_OUT + m] * Wx[(EDGE_DIM + m) * EDGE_DIM + c];
        }
        g_wcomb[idx] = v;
    }
    for (int c = threadIdx.x; c < EDGE_DIM; c += blockDim.x) {
        float v = 0.f;
        #pragma unroll
        for (int m = 0; m < GEO_OUT; m++)
            v += bg[m] * Wx[(EDGE_DIM + m) * EDGE_DIM + c];
        g_cbias[c] = v;
    }
}

// ---------------------------------------------------------------------------
// n_proj = node_feats @ Wn + bn : 64-row tiles, 4x4 register blocking.
// ---------------------------------------------------------------------------
__global__ __launch_bounds__(256) void nproj_kernel(const float* __restrict__ nf,
                                                    const float* __restrict__ Wn,
                                                    const float* __restrict__ bn,
                                                    int N) {
    __shared__ float A[NODE_DIM][68];   // A[k][m] (transposed stage)
    __shared__ float W[NODE_DIM][68];   // W[k][c]
    int tid = threadIdx.x;
    int n0 = blockIdx.x * 64;

    for (int i = tid; i < 64 * 16; i += 256) {
        int k = i >> 4; int c4 = (i & 15) << 2;
        float4 w = *(const float4*)&Wn[k * 64 + c4];
        W[k][c4] = w.x; W[k][c4 + 1] = w.y; W[k][c4 + 2] = w.z; W[k][c4 + 3] = w.w;
    }
    {
        int m = tid >> 2, p = tid & 3;
        int n = n0 + m;
        if (n < N) {
            const float4* row = (const float4*)&nf[(size_t)n * 64];
            #pragma unroll
            for (int i = 0; i < 4; i++) {
                float4 a = row[p * 4 + i];
                int k = (p * 4 + i) * 4;
                A[k][m] = a.x; A[k + 1][m] = a.y; A[k + 2][m] = a.z; A[k + 3][m] = a.w;
            }
        } else {
            #pragma unroll
            for (int i = 0; i < 4; i++) {
                int k = (p * 4 + i) * 4;
                A[k][m] = 0.f; A[k + 1][m] = 0.f; A[k + 2][m] = 0.f; A[k + 3][m] = 0.f;
            }
        }
    }
    __syncthreads();

    int tx = tid & 15, ty = tid >> 4;
    int m0 = tx << 2, c0 = ty << 2;
    float acc[4][4] = {};
    #pragma unroll 8
    for (int k = 0; k < 64; k++) {
        float4 a = *(float4*)&A[k][m0];
        float4 b = *(float4*)&W[k][c0];
        float av[4] = {a.x, a.y, a.z, a.w};
        float bv[4] = {b.x, b.y, b.z, b.w};
        #pragma unroll
        for (int i = 0; i < 4; i++)
            #pragma unroll
            for (int j = 0; j < 4; j++)
                acc[i][j] = fmaf(av[i], bv[j], acc[i][j]);
    }
    float4 bb = *(const float4*)&bn[c0];
    #pragma unroll
    for (int i = 0; i < 4; i++) {
        int n = n0 + m0 + i;
        if (n < N) {
            float4 o;
            o.x = acc[i][0] + bb.x; o.y = acc[i][1] + bb.y;
            o.z = acc[i][2] + bb.z; o.w = acc[i][3] + bb.w;
            *(float4*)&g_nproj[(size_t)n * 64 + c0] = o;
        }
    }
}

// ---------------------------------------------------------------------------
// Edge kernel: 64-edge tiles. Stage gathered join^T [72][64] + Wcomb in smem,
// 4x4 register-blocked GEMM, fused FiLM + relu epilogue, float4 stores.
// ---------------------------------------------------------------------------
__global__ __launch_bounds__(256) void edge_kernel(const float* __restrict__ e_geo,
                                                   float* __restrict__ out,
                                                   int E) {
    __shared__ float J[KTOT][68];   // J[k][edge]
    __shared__ float W[KTOT][68];   // W[k][col]
    __shared__ int   BID[64];
    int tid = threadIdx.x;
    int e0 = blockIdx.x * 64;

    for (int i = tid; i < KTOT * 16; i += 256) {
        int k = i >> 4; int c4 = (i & 15) << 2;
        float4 w = *(const float4*)&g_wcomb[k * 64 + c4];
        W[k][c4] = w.x; W[k][c4 + 1] = w.y; W[k][c4 + 2] = w.z; W[k][c4 + 3] = w.w;
    }
    {
        int m = tid >> 2, p = tid & 3;     // 4 threads per edge
        int e = e0 + m;
        if (e < E) {
            int s = g_src[e], d = g_dst[e];
            const float4* sr = (const float4*)&g_nproj[(size_t)s * 64];
            const float4* dr = (const float4*)&g_nproj[(size_t)d * 64];
            #pragma unroll
            for (int i = 0; i < 4; i++) {
                float4 a = sr[p * 4 + i];
                float4 b = dr[p * 4 + i];
                int k = (p * 4 + i) * 4;
                J[k][m]     = a.x * b.x;
                J[k + 1][m] = a.y * b.y;
                J[k + 2][m] = a.z * b.z;
                J[k + 3][m] = a.w * b.w;
            }
            if (p < 2) {
                float4 g = ((const float4*)&e_geo[(size_t)e * GEO_DIM])[p];
                int k = 64 + p * 4;
                J[k][m] = g.x; J[k + 1][m] = g.y; J[k + 2][m] = g.z; J[k + 3][m] = g.w;
            }
            if (p == 0) BID[m] = g_bid[e];
        } else {
            #pragma unroll
            for (int i = 0; i < 4; i++) {
                int k = (p * 4 + i) * 4;
                J[k][m] = 0.f; J[k + 1][m] = 0.f; J[k + 2][m] = 0.f; J[k + 3][m] = 0.f;
            }
            if (p < 2) {
                int k = 64 + p * 4;
                J[k][m] = 0.f; J[k + 1][m] = 0.f; J[k + 2][m] = 0.f; J[k + 3][m] = 0.f;
            }
            if (p == 0) BID[m] = 0;
        }
    }
    __syncthreads();

    int tx = tid & 15, ty = tid >> 4;
    int m0 = tx << 2, c0 = ty << 2;
    float acc[4][4] = {};
    #pragma unroll 8
    for (int k = 0; k < KTOT; k++) {
        float4 a = *(float4*)&J[k][m0];
        float4 b = *(float4*)&W[k][c0];
        float av[4] = {a.x, a.y, a.z, a.w};
        float bv[4] = {b.x, b.y, b.z, b.w};
        #pragma unroll
        for (int i = 0; i < 4; i++)
            #pragma unroll
            for (int j = 0; j < 4; j++)
                acc[i][j] = fmaf(av[i], bv[j], acc[i][j]);
    }

    float4 cb4 = *(const float4*)&g_cbias[c0];
    float cb[4] = {cb4.x, cb4.y, cb4.z, cb4.w};
    #pragma unroll
    for (int i = 0; i < 4; i++) {
        int e = e0 + m0 + i;
        if (e < E) {
            int b = BID[m0 + i];
            const float* gbp = &g_gamma_beta[b * (2 * EDGE_DIM)];
            float4 g4 = *(const float4*)&gbp[c0];
            float4 b4 = *(const float4*)&gbp[64 + c0];
            float4 o;
            o.x = fmaxf(fmaf(acc[i][0] + cb[0], g4.x, b4.x), 0.f);
            o.y = fmaxf(fmaf(acc[i][1] + cb[1], g4.y, b4.y), 0.f);
            o.z = fmaxf(fmaf(acc[i][2] + cb[2], g4.z, b4.z), 0.f);
            o.w = fmaxf(fmaf(acc[i][3] + cb[3], g4.w, b4.w), 0.f);
            *(float4*)&out[(size_t)e * 64 + c0] = o;
        }
    }
}

// ---------------------------------------------------------------------------
extern "C" void kernel_launch(void* const* d_in, const int* in_sizes, int n_in,
                              void* d_out, int out_size) {
    const float* nf   = (const float*)d_in[0];
    const void*  ei   = d_in[1];
    const float* eg   = (const float*)d_in[2];
    const float* cond = (const float*)d_in[3];
    const void*  bids = d_in[4];
    const float* Wn   = (const float*)d_in[5];
    const float* bn   = (const float*)d_in[6];
    const float* Wg   = (const float*)d_in[7];
    const float* bg   = (const float*)d_in[8];
    const float* Wc   = (const float*)d_in[9];
    const float* bc   = (const float*)d_in[10];
    const float* Wx   = (const float*)d_in[11];
    float* out = (float*)d_out;

    int N = in_sizes[0] / NODE_DIM;
    int E = in_sizes[2] / GEO_DIM;
    int B = in_sizes[3] / COND_DIM;

    detect_kernel<<<1, 256>>>(ei, bids, E);
    convert_kernel<<<(E + 255) / 256, 256>>>(ei, bids, E);
    film_kernel<<<B, 128>>>(cond, Wc, bc);
    wcomb_kernel<<<1, 256>>>(Wg, bg, Wx);
    nproj_kernel<<<(N + 63) / 64, 256>>>(nf, Wn, bn, N);
    edge_kernel<<<(E + 63) / 64, 256>>>(eg, out, E);
}

// round 2
// speedup vs baseline: 1.3319x; 1.3319x over previous
#include <cuda_runtime.h>
#include <stdint.h>

// ---------------------------------------------------------------------------
// EdgeFeat fused pipeline, Round 2: tf32 mma.sync edge GEMM.
//   n_proj = node_feats @ Wn + bn (fp32 scalar GEMM)
//   x      = [nproj[src]*nproj[dst] , e_geo] @ Wcomb + cbias   (K=72, tf32 TC)
//   out    = relu(x * (gamma[bid]+1) + beta[bid])
// Wcomb[0:64]=Wx[0:64]; Wcomb[64:72]=Wg@Wx[64:96]; cbias=bg@Wx[64:96].
// ---------------------------------------------------------------------------

#define NODE_DIM 64
#define EDGE_DIM 64
#define GEO_DIM  8
#define GEO_OUT  32
#define COND_DIM 512
#define KTOT     72
#define MAX_NODES  100000
#define MAX_EDGES  800000
#define MAX_GRAPHS 64

// edge-kernel smem geometry
#define J_STRIDE 76        // mod 32 = 12 -> conflict-free A-frag loads
#define W_STRIDE 72        // mod 32 = 8  -> conflict-free B-frag loads
#define EDGE_TILE 128
#define SMEM_EDGE ((EDGE_TILE * J_STRIDE + KTOT * W_STRIDE) * 4 + EDGE_TILE * 4)

__device__ float g_nproj[MAX_NODES * NODE_DIM];
__device__ int   g_src[MAX_EDGES];
__device__ int   g_dst[MAX_EDGES];
__device__ int   g_bid[MAX_EDGES];
__device__ float g_gamma_beta[MAX_GRAPHS * 2 * EDGE_DIM];
__device__ float g_wcomb[KTOT * EDGE_DIM];   // pre-rounded to tf32 grid
__device__ float g_cbias[EDGE_DIM];
__device__ int   g_ei_is64;
__device__ int   g_bid_is64;

__device__ __forceinline__ unsigned f2tf32(float x) {
    unsigned u;
    asm("cvt.rna.tf32.f32 %0, %1;" : "=r"(u) : "f"(x));
    return u;
}

// ---------------------------------------------------------------------------
// Dtype probe (int64 vs silently-int32 indices).
// ---------------------------------------------------------------------------
__global__ void detect_kernel(const void* ei, const void* bids, int E) {
    __shared__ int bad_ei, bad_bid;
    if (threadIdx.x == 0) { bad_ei = 0; bad_bid = 0; }
    __syncthreads();
    const unsigned long long* p64 = (const unsigned long long*)ei;
    const unsigned long long* b64 = (const unsigned long long*)bids;
    const int samples = 2048;
    long long n_ei = E;
    long long st_e = n_ei / samples; if (st_e < 1) st_e = 1;
    for (int i = threadIdx.x; i < samples; i += blockDim.x) {
        long long idx = (long long)i * st_e;
        if (idx >= n_ei) break;
        if (p64[idx] >> 32) bad_ei = 1;
    }
    long long n_b = E / 2;
    long long st_b = n_b / samples; if (st_b < 1) st_b = 1;
    for (int i = threadIdx.x; i < samples; i += blockDim.x) {
        long long idx = (long long)i * st_b;
        if (idx >= n_b) break;
        if (b64[idx] >> 32) bad_bid = 1;
    }
    __syncthreads();
    if (threadIdx.x == 0) { g_ei_is64 = !bad_ei; g_bid_is64 = !bad_bid; }
}

__global__ void convert_kernel(const void* ei, const void* bids, int E) {
    int e = blockIdx.x * blockDim.x + threadIdx.x;
    if (e >= E) return;
    if (g_ei_is64) {
        const long long* p = (const long long*)ei;
        g_src[e] = (int)p[e];
        g_dst[e] = (int)p[(size_t)E + e];
    } else {
        const int* p = (const int*)ei;
        g_src[e] = p[e];
        g_dst[e] = p[E + e];
    }
    if (g_bid_is64) g_bid[e] = (int)((const long long*)bids)[e];
    else            g_bid[e] = ((const int*)bids)[e];
}

// ---------------------------------------------------------------------------
// FiLM table
// ---------------------------------------------------------------------------
__global__ void film_kernel(const float* __restrict__ cond,
                            const float* __restrict__ Wc,
                            const float* __restrict__ bc) {
    int b = blockIdx.x;
    int j = threadIdx.x;
    const float* crow = cond + (size_t)b * COND_DIM;
    float acc = bc[j];
    #pragma unroll 4
    for (int k = 0; k < COND_DIM; k++)
        acc += crow[k] * Wc[(size_t)k * (2 * EDGE_DIM) + j];
    if (j < EDGE_DIM) acc += 1.0f;
    g_gamma_beta[b * (2 * EDGE_DIM) + j] = acc;
}

// ---------------------------------------------------------------------------
// Wcomb (pre-rounded to tf32) + cbias. Parallelized: 18 blocks x 256.
// ---------------------------------------------------------------------------
__global__ void wcomb_kernel(const float* __restrict__ Wg,
                             const float* __restrict__ bg,
                             const float* __restrict__ Wx) {
    int idx = blockIdx.x * 256 + threadIdx.x;
    if (idx < KTOT * EDGE_DIM) {
        int k = idx / EDGE_DIM, c = idx % EDGE_DIM;
        float v;
        if (k < EDGE_DIM) {
            v = Wx[k * EDGE_DIM + c];
        } else {
            v = 0.f;
            int gk = k - EDGE_DIM;
            #pragma unroll
            for (int m = 0; m < GEO_OUT; m++)
                v += Wg[gk * GEO_OUT + m] * Wx[(EDGE_DIM + m) * EDGE_DIM + c];
        }
        g_wcomb[idx] = __uint_as_float(f2tf32(v));
    }
    if (blockIdx.x == 0 && threadIdx.x < EDGE_DIM) {
        int c = threadIdx.x;
        float v = 0.f;
        #pragma unroll
        for (int m = 0; m < GEO_OUT; m++)
            v += bg[m] * Wx[(EDGE_DIM + m) * EDGE_DIM + c];
        g_cbias[c] = v;
    }
}

// ---------------------------------------------------------------------------
// n_proj (fp32 scalar, kept full precision for accuracy of src*dst products)
// ---------------------------------------------------------------------------
__global__ __launch_bounds__(256) void nproj_kernel(const float* __restrict__ nf,
                                                    const float* __restrict__ Wn,
                                                    const float* __restrict__ bn,
                                                    int N) {
    __shared__ float A[NODE_DIM][68];
    __shared__ float W[NODE_DIM][68];
    int tid = threadIdx.x;
    int n0 = blockIdx.x * 64;

    for (int i = tid; i < 64 * 16; i += 256) {
        int k = i >> 4; int c4 = (i & 15) << 2;
        float4 w = *(const float4*)&Wn[k * 64 + c4];
        W[k][c4] = w.x; W[k][c4 + 1] = w.y; W[k][c4 + 2] = w.z; W[k][c4 + 3] = w.w;
    }
    {
        int m = tid >> 2, p = tid & 3;
        int n = n0 + m;
        if (n < N) {
            const float4* row = (const float4*)&nf[(size_t)n * 64];
            #pragma unroll
            for (int i = 0; i < 4; i++) {
                float4 a = row[p * 4 + i];
                int k = (p * 4 + i) * 4;
                A[k][m] = a.x; A[k + 1][m] = a.y; A[k + 2][m] = a.z; A[k + 3][m] = a.w;
            }
        } else {
            #pragma unroll
            for (int i = 0; i < 4; i++) {
                int k = (p * 4 + i) * 4;
                A[k][m] = 0.f; A[k + 1][m] = 0.f; A[k + 2][m] = 0.f; A[k + 3][m] = 0.f;
            }
        }
    }
    __syncthreads();

    int tx = tid & 15, ty = tid >> 4;
    int m0 = tx << 2, c0 = ty << 2;
    float acc[4][4] = {};
    #pragma unroll 8
    for (int k = 0; k < 64; k++) {
        float4 a = *(float4*)&A[k][m0];
        float4 b = *(float4*)&W[k][c0];
        float av[4] = {a.x, a.y, a.z, a.w};
        float bv[4] = {b.x, b.y, b.z, b.w};
        #pragma unroll
        for (int i = 0; i < 4; i++)
            #pragma unroll
            for (int j = 0; j < 4; j++)
                acc[i][j] = fmaf(av[i], bv[j], acc[i][j]);
    }
    float4 bb = *(const float4*)&bn[c0];
    #pragma unroll
    for (int i = 0; i < 4; i++) {
        int n = n0 + m0 + i;
        if (n < N) {
            float4 o;
            o.x = acc[i][0] + bb.x; o.y = acc[i][1] + bb.y;
            o.z = acc[i][2] + bb.z; o.w = acc[i][3] + bb.w;
            *(float4*)&g_nproj[(size_t)n * 64 + c0] = o;
        }
    }
}

// ---------------------------------------------------------------------------
// Edge kernel: 128-edge tile, tf32 mma.sync m16n8k8, fused FiLM+relu.
// 8 warps: warp_m = wid>>1 (4), warp_n = wid&1 (2); warp tile 32x32.
// J[m][k] tf32 (stride 76), W[k][n] tf32 (stride 72).
// ---------------------------------------------------------------------------
__global__ __launch_bounds__(256) void edge_kernel(const float* __restrict__ e_geo,
                                                   float* __restrict__ out,
                                                   int E) {
    extern __shared__ unsigned sm_u[];
    unsigned* Jt = sm_u;                                   // [128][76]
    unsigned* Wt = Jt + EDGE_TILE * J_STRIDE;              // [72][72]
    int* BID = (int*)(Wt + KTOT * W_STRIDE);               // [128]

    int tid = threadIdx.x;
    int e0 = blockIdx.x * EDGE_TILE;

    // stage Wcomb (already tf32-rounded bits)
    for (int i = tid; i < KTOT * EDGE_DIM; i += 256) {
        int k = i >> 6, n = i & 63;
        Wt[k * W_STRIDE + n] = __float_as_uint(g_wcomb[i]);
    }
    if (tid < EDGE_TILE) {
        int e = e0 + tid;
        BID[tid] = (e < E) ? g_bid[e] : 0;
    }
    // stage J: 2 threads per edge; p=0 -> k[0:32)+geo[64:68), p=1 -> k[32:64)+geo[68:72)
    {
        int m = tid >> 1, p = tid & 1;
        int e = e0 + m;
        unsigned* jrow = Jt + m * J_STRIDE;
        if (e < E) {
            int s = g_src[e], d = g_dst[e];
            const float4* sr = (const float4*)&g_nproj[(size_t)s * 64];
            const float4* dr = (const float4*)&g_nproj[(size_t)d * 64];
            #pragma unroll
            for (int i = 0; i < 8; i++) {
                float4 a = sr[p * 8 + i];
                float4 b = dr[p * 8 + i];
                uint4 v;
                v.x = f2tf32(a.x * b.x);
                v.y = f2tf32(a.y * b.y);
                v.z = f2tf32(a.z * b.z);
                v.w = f2tf32(a.w * b.w);
                *(uint4*)&jrow[(p * 8 + i) * 4] = v;
            }
            float4 g = ((const float4*)&e_geo[(size_t)e * GEO_DIM])[p];
            uint4 v;
            v.x = f2tf32(g.x); v.y = f2tf32(g.y);
            v.z = f2tf32(g.z); v.w = f2tf32(g.w);
            *(uint4*)&jrow[64 + p * 4] = v;
        } else {
            #pragma unroll
            for (int i = 0; i < 8; i++)
                *(uint4*)&jrow[(p * 8 + i) * 4] = make_uint4(0, 0, 0, 0);
            *(uint4*)&jrow[64 + p * 4] = make_uint4(0, 0, 0, 0);
        }
    }
    __syncthreads();

    int lane = tid & 31;
    int wid = tid >> 5;
    int warp_m = wid >> 1;          // 0..3
    int warp_n = wid & 1;           // 0..1
    int gid = lane >> 2;            // 0..7
    int tg = lane & 3;              // 0..3

    float acc[2][4][4];
    #pragma unroll
    for (int mi = 0; mi < 2; mi++)
        #pragma unroll
        for (int nj = 0; nj < 4; nj++)
            #pragma unroll
            for (int q = 0; q < 4; q++) acc[mi][nj][q] = 0.f;

    #pragma unroll
    for (int k0 = 0; k0 < KTOT; k0 += 8) {
        unsigned a[2][4];
        #pragma unroll
        for (int mi = 0; mi < 2; mi++) {
            int m = warp_m * 32 + mi * 16 + gid;
            const unsigned* r0 = Jt + m * J_STRIDE + k0;
            const unsigned* r1 = Jt + (m + 8) * J_STRIDE + k0;
            a[mi][0] = r0[tg];
            a[mi][1] = r1[tg];
            a[mi][2] = r0[tg + 4];
            a[mi][3] = r1[tg + 4];
        }
        unsigned b[4][2];
        #pragma unroll
        for (int nj = 0; nj < 4; nj++) {
            int n = warp_n * 32 + nj * 8 + gid;
            b[nj][0] = Wt[(k0 + tg) * W_STRIDE + n];
            b[nj][1] = Wt[(k0 + tg + 4) * W_STRIDE + n];
        }
        #pragma unroll
        for (int mi = 0; mi < 2; mi++)
            #pragma unroll
            for (int nj = 0; nj < 4; nj++) {
                asm volatile(
                    "mma.sync.aligned.m16n8k8.row.col.f32.tf32.tf32.f32 "
                    "{%0,%1,%2,%3}, {%4,%5,%6,%7}, {%8,%9}, {%0,%1,%2,%3};\n"
                    : "+f"(acc[mi][nj][0]), "+f"(acc[mi][nj][1]),
                      "+f"(acc[mi][nj][2]), "+f"(acc[mi][nj][3])
                    : "r"(a[mi][0]), "r"(a[mi][1]), "r"(a[mi][2]), "r"(a[mi][3]),
                      "r"(b[nj][0]), "r"(b[nj][1]));
            }
    }

    // epilogue: cbias + FiLM + relu, float2 stores
    float2 cb[4];
    #pragma unroll
    for (int nj = 0; nj < 4; nj++) {
        int col = warp_n * 32 + nj * 8 + tg * 2;
        cb[nj] = *(const float2*)&g_cbias[col];
    }
    #pragma unroll
    for (int mi = 0; mi < 2; mi++) {
        #pragma unroll
        for (int h = 0; h < 2; h++) {
            int eloc = warp_m * 32 + mi * 16 + gid + h * 8;
            int e = e0 + eloc;
            if (e < E) {
                const float* gbp = g_gamma_beta + BID[eloc] * (2 * EDGE_DIM);
                #pragma unroll
                for (int nj = 0; nj < 4; nj++) {
                    int col = warp_n * 32 + nj * 8 + tg * 2;
                    float2 ga = *(const float2*)&gbp[col];
                    float2 be = *(const float2*)&gbp[64 + col];
                    float x0 = acc[mi][nj][h * 2 + 0] + cb[nj].x;
                    float x1 = acc[mi][nj][h * 2 + 1] + cb[nj].y;
                    float2 o;
                    o.x = fmaxf(fmaf(x0, ga.x, be.x), 0.f);
                    o.y = fmaxf(fmaf(x1, ga.y, be.y), 0.f);
                    *(float2*)&out[(size_t)e * 64 + col] = o;
                }
            }
        }
    }
}

// ---------------------------------------------------------------------------
extern "C" void kernel_launch(void* const* d_in, const int* in_sizes, int n_in,
                              void* d_out, int out_size) {
    const float* nf   = (const float*)d_in[0];
    const void*  ei   = d_in[1];
    const float* eg   = (const float*)d_in[2];
    const float* cond = (const float*)d_in[3];
    const void*  bids = d_in[4];
    const float* Wn   = (const float*)d_in[5];
    const float* bn   = (const float*)d_in[6];
    const float* Wg   = (const float*)d_in[7];
    const float* bg   = (const float*)d_in[8];
    const float* Wc   = (const float*)d_in[9];
    const float* bc   = (const float*)d_in[10];
    const float* Wx   = (const float*)d_in[11];
    float* out = (float*)d_out;

    int N = in_sizes[0] / NODE_DIM;
    int E = in_sizes[2] / GEO_DIM;
    int B = in_sizes[3] / COND_DIM;

    static int smem_set = 0;
    if (!smem_set) {
        cudaFuncSetAttribute(edge_kernel,
                             cudaFuncAttributeMaxDynamicSharedMemorySize,
                             SMEM_EDGE);
        smem_set = 1;
    }

    detect_kernel<<<1, 256>>>(ei, bids, E);
    convert_kernel<<<(E + 255) / 256, 256>>>(ei, bids, E);
    film_kernel<<<B, 128>>>(cond, Wc, bc);
    wcomb_kernel<<<(KTOT * EDGE_DIM + 255) / 256, 256>>>(Wg, bg, Wx);
    nproj_kernel<<<(N + 63) / 64, 256>>>(nf, Wn, bn, N);
    edge_kernel<<<(E + EDGE_TILE - 1) / EDGE_TILE, 256, SMEM_EDGE>>>(eg, out, E);
}

// round 3
// speedup vs baseline: 1.5989x; 1.2005x over previous
#include <cuda_runtime.h>
#include <stdint.h>

// ---------------------------------------------------------------------------
// EdgeFeat fused pipeline, Round 3: coalesced row-gather + shfl product.
//   n_proj = node_feats @ Wn + bn (fp32 scalar GEMM)
//   x      = [nproj[src]*nproj[dst] , e_geo] @ Wcomb + cbias   (K=72, tf32 TC)
//   out    = relu(x * (gamma[bid]+1) + beta[bid])
// ---------------------------------------------------------------------------

#define NODE_DIM 64
#define EDGE_DIM 64
#define GEO_DIM  8
#define GEO_OUT  32
#define COND_DIM 512
#define KTOT     72
#define MAX_NODES  100000
#define MAX_EDGES  800000
#define MAX_GRAPHS 64

#define J_STRIDE 76        // mod 32 = 12 -> conflict-free A-frag LDS
#define W_STRIDE 72        // mod 32 = 8  -> conflict-free B-frag LDS
#define EDGE_TILE 128
#define SMEM_EDGE ((EDGE_TILE * J_STRIDE + KTOT * W_STRIDE) * 4)

__device__ float g_nproj[MAX_NODES * NODE_DIM];
__device__ float g_gamma_beta[MAX_GRAPHS * 2 * EDGE_DIM];
__device__ float g_wcomb[KTOT * EDGE_DIM];   // pre-rounded to tf32 grid
__device__ float g_cbias[EDGE_DIM];
__device__ int   g_ei_is64;
__device__ int   g_bid_is64;

__device__ __forceinline__ unsigned f2tf32(float x) {
    unsigned u;
    asm("cvt.rna.tf32.f32 %0, %1;" : "=r"(u) : "f"(x));
    return u;
}

// ---------------------------------------------------------------------------
// Dtype probe (int64 vs silently-int32 indices). Values < 2^17 -> nonzero
// high word in a sampled int64 slot proves int32 packing. Samples stay within
// the smaller dtype's byte footprint.
// ---------------------------------------------------------------------------
__global__ void detect_kernel(const void* ei, const void* bids, int E) {
    __shared__ int bad_ei, bad_bid;
    if (threadIdx.x == 0) { bad_ei = 0; bad_bid = 0; }
    __syncthreads();
    const unsigned long long* p64 = (const unsigned long long*)ei;
    const unsigned long long* b64 = (const unsigned long long*)bids;
    const int samples = 2048;
    long long n_ei = E;
    long long st_e = n_ei / samples; if (st_e < 1) st_e = 1;
    for (int i = threadIdx.x; i < samples; i += blockDim.x) {
        long long idx = (long long)i * st_e;
        if (idx >= n_ei) break;
        if (p64[idx] >> 32) bad_ei = 1;
    }
    long long n_b = E / 2;
    long long st_b = n_b / samples; if (st_b < 1) st_b = 1;
    for (int i = threadIdx.x; i < samples; i += blockDim.x) {
        long long idx = (long long)i * st_b;
        if (idx >= n_b) break;
        if (b64[idx] >> 32) bad_bid = 1;
    }
    __syncthreads();
    if (threadIdx.x == 0) { g_ei_is64 = !bad_ei; g_bid_is64 = !bad_bid; }
}

// ---------------------------------------------------------------------------
// Fused FiLM table (blocks 0..B-1) + Wcomb/cbias (blocks B..B+17).
// ---------------------------------------------------------------------------
__global__ void prep_kernel(const float* __restrict__ cond,
                            const float* __restrict__ Wc,
                            const float* __restrict__ bc,
                            const float* __restrict__ Wg,
                            const float* __restrict__ bg,
                            const float* __restrict__ Wx,
                            int B) {
    if ((int)blockIdx.x < B) {
        // FiLM: 256 threads, 2-way k-split reduction
        __shared__ float part[2 * EDGE_DIM];
        int b = blockIdx.x;
        int j = threadIdx.x & 127;
        int h = threadIdx.x >> 7;
        const float* crow = cond + (size_t)b * COND_DIM + h * 256;
        float acc = 0.f;
        #pragma unroll 4
        for (int k = 0; k < 256; k++)
            acc += crow[k] * Wc[(size_t)(h * 256 + k) * (2 * EDGE_DIM) + j];
        if (h == 1) part[j] = acc;
        __syncthreads();
        if (h == 0) {
            acc += part[j] + bc[j];
            if (j < EDGE_DIM) acc += 1.0f;
            g_gamma_beta[b * (2 * EDGE_DIM) + j] = acc;
        }
    } else {
        int idx = ((int)blockIdx.x - B) * 256 + threadIdx.x;
        if (idx < KTOT * EDGE_DIM) {
            int k = idx / EDGE_DIM, c = idx % EDGE_DIM;
            float v;
            if (k < EDGE_DIM) {
                v = Wx[k * EDGE_DIM + c];
            } else {
                v = 0.f;
                int gk = k - EDGE_DIM;
                #pragma unroll
                for (int m = 0; m < GEO_OUT; m++)
                    v += Wg[gk * GEO_OUT + m] * Wx[(EDGE_DIM + m) * EDGE_DIM + c];
            }
            g_wcomb[idx] = __uint_as_float(f2tf32(v));
        }
        if ((int)blockIdx.x == B && threadIdx.x < EDGE_DIM) {
            int c = threadIdx.x;
            float v = 0.f;
            #pragma unroll
            for (int m = 0; m < GEO_OUT; m++)
                v += bg[m] * Wx[(EDGE_DIM + m) * EDGE_DIM + c];
            g_cbias[c] = v;
        }
    }
}

// ---------------------------------------------------------------------------
// n_proj (fp32 scalar — kept full precision so src*dst products stay clean)
// ---------------------------------------------------------------------------
__global__ __launch_bounds__(256) void nproj_kernel(const float* __restrict__ nf,
                                                    const float* __restrict__ Wn,
                                                    const float* __restrict__ bn,
                                                    int N) {
    __shared__ float A[NODE_DIM][68];
    __shared__ float W[NODE_DIM][68];
    int tid = threadIdx.x;
    int n0 = blockIdx.x * 64;

    for (int i = tid; i < 64 * 16; i += 256) {
        int k = i >> 4; int c4 = (i & 15) << 2;
        float4 w = *(const float4*)&Wn[k * 64 + c4];
        W[k][c4] = w.x; W[k][c4 + 1] = w.y; W[k][c4 + 2] = w.z; W[k][c4 + 3] = w.w;
    }
    {
        int m = tid >> 2, p = tid & 3;
        int n = n0 + m;
        if (n < N) {
            const float4* row = (const float4*)&nf[(size_t)n * 64];
            #pragma unroll
            for (int i = 0; i < 4; i++) {
                float4 a = row[p * 4 + i];
                int k = (p * 4 + i) * 4;
                A[k][m] = a.x; A[k + 1][m] = a.y; A[k + 2][m] = a.z; A[k + 3][m] = a.w;
            }
        } else {
            #pragma unroll
            for (int i = 0; i < 4; i++) {
                int k = (p * 4 + i) * 4;
                A[k][m] = 0.f; A[k + 1][m] = 0.f; A[k + 2][m] = 0.f; A[k + 3][m] = 0.f;
            }
        }
    }
    __syncthreads();

    int tx = tid & 15, ty = tid >> 4;
    int m0 = tx << 2, c0 = ty << 2;
    float acc[4][4] = {};
    #pragma unroll 8
    for (int k = 0; k < 64; k++) {
        float4 a = *(float4*)&A[k][m0];
        float4 b = *(float4*)&W[k][c0];
        float av[4] = {a.x, a.y, a.z, a.w};
        float bv[4] = {b.x, b.y, b.z, b.w};
        #pragma unroll
        for (int i = 0; i < 4; i++)
            #pragma unroll
            for (int j = 0; j < 4; j++)
                acc[i][j] = fmaf(av[i], bv[j], acc[i][j]);
    }
    float4 bb = *(const float4*)&bn[c0];
    #pragma unroll
    for (int i = 0; i < 4; i++) {
        int n = n0 + m0 + i;
        if (n < N) {
            float4 o;
            o.x = acc[i][0] + bb.x; o.y = acc[i][1] + bb.y;
            o.z = acc[i][2] + bb.z; o.w = acc[i][3] + bb.w;
            *(float4*)&g_nproj[(size_t)n * 64 + c0] = o;
        }
    }
}

// ---------------------------------------------------------------------------
// Edge kernel, coalesced gather:
//   warp iteration t handles ONE edge: lanes 0-15 read the 16 contiguous 16B
//   chunks of nproj[src], lanes 16-31 read nproj[dst]  (nL = 4 lines/LDG).
//   shfl_xor(16) pairs chunks; lanes 0-15 write tf32 products to smem.
// Then 8-warp m16n8k8 tf32 mma (warp tile 32x32), fused FiLM+relu epilogue.
// ---------------------------------------------------------------------------
__global__ __launch_bounds__(256, 3) void edge_kernel(const void* __restrict__ ei,
                                                      const void* __restrict__ bids,
                                                      const float* __restrict__ e_geo,
                                                      float* __restrict__ out,
                                                      int E) {
    extern __shared__ unsigned sm_u[];
    unsigned* Jt = sm_u;                                   // [128][76]
    unsigned* Wt = Jt + EDGE_TILE * J_STRIDE;              // [72][72]

    int tid = threadIdx.x;
    int e0 = blockIdx.x * EDGE_TILE;
    int lane = tid & 31;
    int wid = tid >> 5;
    const int ei64 = g_ei_is64;

    // stage Wcomb (tf32 bits)
    for (int i = tid; i < KTOT * EDGE_DIM; i += 256) {
        int k = i >> 6, n = i & 63;
        Wt[k * W_STRIDE + n] = __float_as_uint(g_wcomb[i]);
    }

    // gather + product staging: warp handles 16 edges
    {
        int ebase = e0 + wid * 16;
        int lhalf = lane >> 4;          // 0 = src half, 1 = dst half
        int c = lane & 15;              // 16B chunk within row
        // preload this warp's 16 edge indices (lane c holds edge ebase+c)
        int row = 0;
        {
            long long e = ebase + c;
            if (e < E) {
                if (ei64) {
                    const long long* p = (const long long*)ei;
                    row = (int)p[lhalf ? ((long long)E + e) : e];
                } else {
                    const int* p = (const int*)ei;
                    row = p[lhalf ? (E + (int)e) : (int)e];
                }
            }
        }
        #pragma unroll
        for (int t = 0; t < 16; t++) {
            int r = __shfl_sync(0xffffffffu, row, lhalf * 16 + t);
            float4 v = *(const float4*)&g_nproj[(size_t)r * 64 + c * 4];
            float4 pv;
            pv.x = __shfl_xor_sync(0xffffffffu, v.x, 16);
            pv.y = __shfl_xor_sync(0xffffffffu, v.y, 16);
            pv.z = __shfl_xor_sync(0xffffffffu, v.z, 16);
            pv.w = __shfl_xor_sync(0xffffffffu, v.w, 16);
            if (lhalf == 0) {
                int m = wid * 16 + t;
                bool valid = (e0 + m) < E;
                uint4 o;
                o.x = valid ? f2tf32(v.x * pv.x) : 0u;
                o.y = valid ? f2tf32(v.y * pv.y) : 0u;
                o.z = valid ? f2tf32(v.z * pv.z) : 0u;
                o.w = valid ? f2tf32(v.w * pv.w) : 0u;
                *(uint4*)&Jt[m * J_STRIDE + c * 4] = o;
            }
        }
    }
    // geo tail: thread -> (edge, half-row)
    {
        int m = tid >> 1, part = tid & 1;
        int e = e0 + m;
        uint4 o = make_uint4(0, 0, 0, 0);
        if (e < E) {
            float4 g = ((const float4*)&e_geo[(size_t)e * GEO_DIM])[part];
            o.x = f2tf32(g.x); o.y = f2tf32(g.y);
            o.z = f2tf32(g.z); o.w = f2tf32(g.w);
        }
        *(uint4*)&Jt[m * J_STRIDE + 64 + part * 4] = o;
    }
    __syncthreads();

    int warp_m = wid >> 1;          // 0..3
    int warp_n = wid & 1;           // 0..1
    int gid = lane >> 2;            // 0..7
    int tg = lane & 3;              // 0..3

    float acc[2][4][4];
    #pragma unroll
    for (int mi = 0; mi < 2; mi++)
        #pragma unroll
        for (int nj = 0; nj < 4; nj++)
            #pragma unroll
            for (int q = 0; q < 4; q++) acc[mi][nj][q] = 0.f;

    #pragma unroll
    for (int k0 = 0; k0 < KTOT; k0 += 8) {
        unsigned a[2][4];
        #pragma unroll
        for (int mi = 0; mi < 2; mi++) {
            int m = warp_m * 32 + mi * 16 + gid;
            const unsigned* r0 = Jt + m * J_STRIDE + k0;
            const unsigned* r1 = Jt + (m + 8) * J_STRIDE + k0;
            a[mi][0] = r0[tg];
            a[mi][1] = r1[tg];
            a[mi][2] = r0[tg + 4];
            a[mi][3] = r1[tg + 4];
        }
        unsigned b[4][2];
        #pragma unroll
        for (int nj = 0; nj < 4; nj++) {
            int n = warp_n * 32 + nj * 8 + gid;
            b[nj][0] = Wt[(k0 + tg) * W_STRIDE + n];
            b[nj][1] = Wt[(k0 + tg + 4) * W_STRIDE + n];
        }
        #pragma unroll
        for (int mi = 0; mi < 2; mi++)
            #pragma unroll
            for (int nj = 0; nj < 4; nj++) {
                asm volatile(
                    "mma.sync.aligned.m16n8k8.row.col.f32.tf32.tf32.f32 "
                    "{%0,%1,%2,%3}, {%4,%5,%6,%7}, {%8,%9}, {%0,%1,%2,%3};\n"
                    : "+f"(acc[mi][nj][0]), "+f"(acc[mi][nj][1]),
                      "+f"(acc[mi][nj][2]), "+f"(acc[mi][nj][3])
                    : "r"(a[mi][0]), "r"(a[mi][1]), "r"(a[mi][2]), "r"(a[mi][3]),
                      "r"(b[nj][0]), "r"(b[nj][1]));
            }
    }

    // epilogue: cbias + FiLM + relu
    const int bid64 = g_bid_is64;
    float2 cb[4];
    #pragma unroll
    for (int nj = 0; nj < 4; nj++) {
        int col = warp_n * 32 + nj * 8 + tg * 2;
        cb[nj] = *(const float2*)&g_cbias[col];
    }
    #pragma unroll
    for (int mi = 0; mi < 2; mi++) {
        #pragma unroll
        for (int h = 0; h < 2; h++) {
            int eloc = warp_m * 32 + mi * 16 + gid + h * 8;
            int e = e0 + eloc;
            if (e < E) {
                int bb;
                if (bid64) bb = (int)((const long long*)bids)[e];
                else       bb = ((const int*)bids)[e];
                const float* gbp = g_gamma_beta + bb * (2 * EDGE_DIM);
                #pragma unroll
                for (int nj = 0; nj < 4; nj++) {
                    int col = warp_n * 32 + nj * 8 + tg * 2;
                    float2 ga = *(const float2*)&gbp[col];
                    float2 be = *(const float2*)&gbp[64 + col];
                    float x0 = acc[mi][nj][h * 2 + 0] + cb[nj].x;
                    float x1 = acc[mi][nj][h * 2 + 1] + cb[nj].y;
                    float2 o;
                    o.x = fmaxf(fmaf(x0, ga.x, be.x), 0.f);
                    o.y = fmaxf(fmaf(x1, ga.y, be.y), 0.f);
                    *(float2*)&out[(size_t)e * 64 + col] = o;
                }
            }
        }
    }
}

// ---------------------------------------------------------------------------
extern "C" void kernel_launch(void* const* d_in, const int* in_sizes, int n_in,
                              void* d_out, int out_size) {
    const float* nf   = (const float*)d_in[0];
    const void*  ei   = d_in[1];
    const float* eg   = (const float*)d_in[2];
    const float* cond = (const float*)d_in[3];
    const void*  bids = d_in[4];
    const float* Wn   = (const float*)d_in[5];
    const float* bn   = (const float*)d_in[6];
    const float* Wg   = (const float*)d_in[7];
    const float* bg   = (const float*)d_in[8];
    const float* Wc   = (const float*)d_in[9];
    const float* bc   = (const float*)d_in[10];
    const float* Wx   = (const float*)d_in[11];
    float* out = (float*)d_out;

    int N = in_sizes[0] / NODE_DIM;
    int E = in_sizes[2] / GEO_DIM;
    int B = in_sizes[3] / COND_DIM;

    static int smem_set = 0;
    if (!smem_set) {
        cudaFuncSetAttribute(edge_kernel,
                             cudaFuncAttributeMaxDynamicSharedMemorySize,
                             SMEM_EDGE);
        smem_set = 1;
    }

    detect_kernel<<<1, 1024>>>(ei, bids, E);
    prep_kernel<<<B + (KTOT * EDGE_DIM + 255) / 256, 256>>>(cond, Wc, bc, Wg, bg, Wx, B);
    nproj_kernel<<<(N + 63) / 64, 256>>>(nf, Wn, bn, N);
    edge_kernel<<<(E + EDGE_TILE - 1) / EDGE_TILE, 256, SMEM_EDGE>>>(ei, bids, eg, out, E);
}

// round 4
// speedup vs baseline: 1.9417x; 1.2144x over previous
#include <cuda_runtime.h>
#include <cuda_fp16.h>
#include <stdint.h>

// ---------------------------------------------------------------------------
// EdgeFeat, Round 4: persistent warp-specialized fp16 MMA pipeline.
//   n_proj = node_feats @ Wn + bn                    (fp32 scalar GEMM)
//   x      = [nproj[src]*nproj[dst], e_geo] @ Wcomb  (K=72->80, fp16 m16n8k16)
//   out    = relu((x + cbias) * gamma[bid] + beta[bid])
// ---------------------------------------------------------------------------

#define NODE_DIM 64
#define EDGE_DIM 64
#define GEO_DIM  8
#define GEO_OUT  32
#define COND_DIM 512
#define KTOT     72
#define KPAD     80            // 5 x k16 mma steps
#define MAX_NODES  100000
#define MAX_EDGES  800000
#define MAX_GRAPHS 64

#define EDGE_TILE 128
#define JH_STRIDE 88           // halfs; word-bank pattern 12*gid+tg conflict-free
#define WT_STRIDE 88           // halfs
#define GB_STRIDE 132          // floats
// smem layout (bytes)
#define SM_J_OFF   0
#define SM_J_BYTES (2 * EDGE_TILE * JH_STRIDE * 2)          // 45056
#define SM_W_OFF   (SM_J_OFF + SM_J_BYTES)
#define SM_W_BYTES (64 * WT_STRIDE * 2)                     // 11264
#define SM_GB_OFF  (SM_W_OFF + SM_W_BYTES)
#define SM_GB_BYTES (64 * GB_STRIDE * 4)                    // 33792
#define SM_TOTAL   (SM_GB_OFF + SM_GB_BYTES)                // 90112

__device__ float  g_nproj[MAX_NODES * NODE_DIM];
__device__ float  g_gamma_beta[MAX_GRAPHS * 2 * EDGE_DIM];
__device__ __half g_wcomb_h[KPAD * EDGE_DIM];   // [k][n], k>=72 zero
__device__ float  g_cbias[EDGE_DIM];
__device__ int    g_ei_is64;
__device__ int    g_bid_is64;

struct __align__(8) Half4 { __half2 lo, hi; };

// ---------------------------------------------------------------------------
// Dtype probe (int64 vs silently-int32 indices); values < 2^17.
// ---------------------------------------------------------------------------
__global__ void detect_kernel(const void* ei, const void* bids, int E) {
    __shared__ int bad_ei, bad_bid;
    if (threadIdx.x == 0) { bad_ei = 0; bad_bid = 0; }
    __syncthreads();
    const unsigned long long* p64 = (const unsigned long long*)ei;
    const unsigned long long* b64 = (const unsigned long long*)bids;
    const int samples = 2048;
    long long n_ei = E;
    long long st_e = n_ei / samples; if (st_e < 1) st_e = 1;
    for (int i = threadIdx.x; i < samples; i += blockDim.x) {
        long long idx = (long long)i * st_e;
        if (idx >= n_ei) break;
        if (p64[idx] >> 32) bad_ei = 1;
    }
    long long n_b = E / 2;
    long long st_b = n_b / samples; if (st_b < 1) st_b = 1;
    for (int i = threadIdx.x; i < samples; i += blockDim.x) {
        long long idx = (long long)i * st_b;
        if (idx >= n_b) break;
        if (b64[idx] >> 32) bad_bid = 1;
    }
    __syncthreads();
    if (threadIdx.x == 0) { g_ei_is64 = !bad_ei; g_bid_is64 = !bad_bid; }
}

// ---------------------------------------------------------------------------
// prep: FiLM table (blocks 0..B-1) + Wcomb(fp16, padded)/cbias (blocks B..)
// ---------------------------------------------------------------------------
__global__ void prep_kernel(const float* __restrict__ cond,
                            const float* __restrict__ Wc,
                            const float* __restrict__ bc,
                            const float* __restrict__ Wg,
                            const float* __restrict__ bg,
                            const float* __restrict__ Wx,
                            int B) {
    if ((int)blockIdx.x < B) {
        __shared__ float part[2 * EDGE_DIM];
        int b = blockIdx.x;
        int j = threadIdx.x & 127;
        int h = threadIdx.x >> 7;
        const float* crow = cond + (size_t)b * COND_DIM + h * 256;
        float acc = 0.f;
        #pragma unroll 4
        for (int k = 0; k < 256; k++)
            acc += crow[k] * Wc[(size_t)(h * 256 + k) * (2 * EDGE_DIM) + j];
        if (h == 1) part[j] = acc;
        __syncthreads();
        if (h == 0) {
            acc += part[j] + bc[j];
            if (j < EDGE_DIM) acc += 1.0f;
            g_gamma_beta[b * (2 * EDGE_DIM) + j] = acc;
        }
    } else {
        int idx = ((int)blockIdx.x - B) * 256 + threadIdx.x;
        if (idx < KPAD * EDGE_DIM) {
            int k = idx >> 6, c = idx & 63;
            float v = 0.f;
            if (k < EDGE_DIM) {
                v = Wx[k * EDGE_DIM + c];
            } else if (k < KTOT) {
                int gk = k - EDGE_DIM;
                #pragma unroll
                for (int m = 0; m < GEO_OUT; m++)
                    v += Wg[gk * GEO_OUT + m] * Wx[(EDGE_DIM + m) * EDGE_DIM + c];
            }
            g_wcomb_h[idx] = __float2half_rn(v);
        }
        if ((int)blockIdx.x == B && threadIdx.x < EDGE_DIM) {
            int c = threadIdx.x;
            float v = 0.f;
            #pragma unroll
            for (int m = 0; m < GEO_OUT; m++)
                v += bg[m] * Wx[(EDGE_DIM + m) * EDGE_DIM + c];
            g_cbias[c] = v;
        }
    }
}

// ---------------------------------------------------------------------------
// n_proj (fp32 scalar)
// ---------------------------------------------------------------------------
__global__ __launch_bounds__(256) void nproj_kernel(const float* __restrict__ nf,
                                                    const float* __restrict__ Wn,
                                                    const float* __restrict__ bn,
                                                    int N) {
    __shared__ float A[NODE_DIM][68];
    __shared__ float W[NODE_DIM][68];
    int tid = threadIdx.x;
    int n0 = blockIdx.x * 64;

    for (int i = tid; i < 64 * 16; i += 256) {
        int k = i >> 4; int c4 = (i & 15) << 2;
        float4 w = *(const float4*)&Wn[k * 64 + c4];
        W[k][c4] = w.x; W[k][c4 + 1] = w.y; W[k][c4 + 2] = w.z; W[k][c4 + 3] = w.w;
    }
    {
        int m = tid >> 2, p = tid & 3;
        int n = n0 + m;
        if (n < N) {
            const float4* row = (const float4*)&nf[(size_t)n * 64];
            #pragma unroll
            for (int i = 0; i < 4; i++) {
                float4 a = row[p * 4 + i];
                int k = (p * 4 + i) * 4;
                A[k][m] = a.x; A[k + 1][m] = a.y; A[k + 2][m] = a.z; A[k + 3][m] = a.w;
            }
        } else {
            #pragma unroll
            for (int i = 0; i < 4; i++) {
                int k = (p * 4 + i) * 4;
                A[k][m] = 0.f; A[k + 1][m] = 0.f; A[k + 2][m] = 0.f; A[k + 3][m] = 0.f;
            }
        }
    }
    __syncthreads();

    int tx = tid & 15, ty = tid >> 4;
    int m0 = tx << 2, c0 = ty << 2;
    float acc[4][4] = {};
    #pragma unroll 8
    for (int k = 0; k < 64; k++) {
        float4 a = *(float4*)&A[k][m0];
        float4 b = *(float4*)&W[k][c0];
        float av[4] = {a.x, a.y, a.z, a.w};
        float bv[4] = {b.x, b.y, b.z, b.w};
        #pragma unroll
        for (int i = 0; i < 4; i++)
            #pragma unroll
            for (int j = 0; j < 4; j++)
                acc[i][j] = fmaf(av[i], bv[j], acc[i][j]);
    }
    float4 bb = *(const float4*)&bn[c0];
    #pragma unroll
    for (int i = 0; i < 4; i++) {
        int n = n0 + m0 + i;
        if (n < N) {
            float4 o;
            o.x = acc[i][0] + bb.x; o.y = acc[i][1] + bb.y;
            o.z = acc[i][2] + bb.z; o.w = acc[i][3] + bb.w;
            *(float4*)&g_nproj[(size_t)n * 64 + c0] = o;
        }
    }
}

// ---------------------------------------------------------------------------
// Edge kernel: persistent, warp-specialized producer/consumer pipeline.
// Named barriers: FULL(buf)=1+buf, EMPTY(buf)=3+buf; 128 arrive + 128 sync.
// ---------------------------------------------------------------------------
#define NB_SYNC(id)   asm volatile("bar.sync %0, 256;" :: "r"(id) : "memory")
#define NB_ARRIVE(id) asm volatile("bar.arrive %0, 256;" :: "r"(id) : "memory")

__global__ __launch_bounds__(256, 2) void edge_kernel(const void* __restrict__ ei,
                                                      const void* __restrict__ bids,
                                                      const float* __restrict__ e_geo,
                                                      float* __restrict__ out,
                                                      int E, int ntiles) {
    extern __shared__ char sm[];
    __half* Jbase = (__half*)(sm + SM_J_OFF);
    __half* Wt    = (__half*)(sm + SM_W_OFF);
    float*  SGB   = (float*)(sm + SM_GB_OFF);

    int tid = threadIdx.x;
    int lane = tid & 31;
    int wid = tid >> 5;
    const int ei64 = g_ei_is64;
    const int bid64 = g_bid_is64;

    // ---- one-time staging ----
    for (int i = tid; i < KPAD * EDGE_DIM; i += 256) {
        int k = i >> 6, n = i & 63;
        Wt[n * WT_STRIDE + k] = g_wcomb_h[i];
    }
    for (int i = tid; i < 64 * 2 * EDGE_DIM; i += 256) {
        int b = i >> 7, c = i & 127;
        SGB[b * GB_STRIDE + c] = g_gamma_beta[i];
    }
    {   // zero J pad cols [72,80) in both buffers
        __half z = __float2half_rn(0.f);
        for (int i = tid; i < 2 * EDGE_TILE * 8; i += 256) {
            int buf = i >> 10, r = i & 1023;
            int m = r >> 3, j = r & 7;
            Jbase[buf * EDGE_TILE * JH_STRIDE + m * JH_STRIDE + 72 + j] = z;
        }
    }
    __syncthreads();

    if (wid < 4) {
        // ================= PRODUCER =================
        int w = wid;
        int halfsel = lane >> 4;
        int c = lane & 15;
        int i = 0;
        for (int tile = blockIdx.x; tile < ntiles; tile += gridDim.x, i++) {
            int buf = i & 1;
            if (i >= 2) NB_SYNC(3 + buf);
            __half* J = Jbase + buf * (EDGE_TILE * JH_STRIDE);
            int e0 = tile * EDGE_TILE;
            int ebase = e0 + w * 32;

            // preload this warp's 32 edge idx pairs (lane l -> edge ebase+l)
            int rs = 0, rd = 0;
            {
                long long ee = (long long)ebase + lane;
                if (ee < E) {
                    if (ei64) {
                        const long long* p = (const long long*)ei;
                        rs = (int)p[ee];
                        rd = (int)p[(long long)E + ee];
                    } else {
                        const int* p = (const int*)ei;
                        rs = p[(int)ee];
                        rd = p[E + (int)ee];
                    }
                }
            }
            __half2 z2 = __float2half2_rn(0.f);
            #pragma unroll
            for (int t = 0; t < 16; t++) {
                int sl = 2 * t + halfsel;
                int r1 = __shfl_sync(0xffffffffu, rs, sl);
                int r2 = __shfl_sync(0xffffffffu, rd, sl);
                int m = w * 32 + sl;
                bool valid = (e0 + m) < E;
                float4 v1 = *(const float4*)&g_nproj[(size_t)r1 * 64 + c * 4];
                float4 v2 = *(const float4*)&g_nproj[(size_t)r2 * 64 + c * 4];
                Half4 hv;
                hv.lo = valid ? __floats2half2_rn(v1.x * v2.x, v1.y * v2.y) : z2;
                hv.hi = valid ? __floats2half2_rn(v1.z * v2.z, v1.w * v2.w) : z2;
                *(Half4*)&J[m * JH_STRIDE + c * 4] = hv;
            }
            // geo cols [64,72)
            #pragma unroll
            for (int pass = 0; pass < 2; pass++) {
                int eloc = w * 32 + pass * 16 + (lane >> 1);
                int part = lane & 1;
                int e = e0 + eloc;
                Half4 hv; hv.lo = z2; hv.hi = z2;
                if (e < E) {
                    float4 g = *(const float4*)&e_geo[(size_t)e * GEO_DIM + part * 4];
                    hv.lo = __floats2half2_rn(g.x, g.y);
                    hv.hi = __floats2half2_rn(g.z, g.w);
                }
                *(Half4*)&J[eloc * JH_STRIDE + 64 + part * 4] = hv;
            }
            asm volatile("membar.cta;" ::: "memory");
            NB_ARRIVE(1 + buf);
        }
    } else {
        // ================= CONSUMER =================
        int cw = wid - 4;
        int gid = lane >> 2;
        int tg = lane & 3;

        float2 cb[8];
        #pragma unroll
        for (int nj = 0; nj < 8; nj++)
            cb[nj] = *(const float2*)&g_cbias[nj * 8 + tg * 2];

        int i = 0;
        for (int tile = blockIdx.x; tile < ntiles; tile += gridDim.x, i++) {
            int buf = i & 1;
            NB_SYNC(1 + buf);
            const __half* J = Jbase + buf * (EDGE_TILE * JH_STRIDE);
            int e0 = tile * EDGE_TILE;

            float acc[2][8][4];
            #pragma unroll
            for (int mi = 0; mi < 2; mi++)
                #pragma unroll
                for (int nj = 0; nj < 8; nj++)
                    #pragma unroll
                    for (int q = 0; q < 4; q++) acc[mi][nj][q] = 0.f;

            #pragma unroll
            for (int ks = 0; ks < 5; ks++) {
                unsigned a[2][4];
                #pragma unroll
                for (int mi = 0; mi < 2; mi++) {
                    int row = cw * 32 + mi * 16 + gid;
                    const __half* r0 = J + row * JH_STRIDE + ks * 16;
                    const __half* r1 = J + (row + 8) * JH_STRIDE + ks * 16;
                    a[mi][0] = *(const unsigned*)&r0[tg * 2];
                    a[mi][1] = *(const unsigned*)&r1[tg * 2];
                    a[mi][2] = *(const unsigned*)&r0[8 + tg * 2];
                    a[mi][3] = *(const unsigned*)&r1[8 + tg * 2];
                }
                unsigned b[8][2];
                #pragma unroll
                for (int nj = 0; nj < 8; nj++) {
                    int n = nj * 8 + gid;
                    const __half* wr = Wt + n * WT_STRIDE + ks * 16;
                    b[nj][0] = *(const unsigned*)&wr[tg * 2];
                    b[nj][1] = *(const unsigned*)&wr[8 + tg * 2];
                }
                #pragma unroll
                for (int mi = 0; mi < 2; mi++)
                    #pragma unroll
                    for (int nj = 0; nj < 8; nj++) {
                        asm volatile(
                            "mma.sync.aligned.m16n8k16.row.col.f32.f16.f16.f32 "
                            "{%0,%1,%2,%3}, {%4,%5,%6,%7}, {%8,%9}, {%0,%1,%2,%3};\n"
                            : "+f"(acc[mi][nj][0]), "+f"(acc[mi][nj][1]),
                              "+f"(acc[mi][nj][2]), "+f"(acc[mi][nj][3])
                            : "r"(a[mi][0]), "r"(a[mi][1]), "r"(a[mi][2]), "r"(a[mi][3]),
                              "r"(b[nj][0]), "r"(b[nj][1]));
                    }
            }
            // buffer consumed -> release early; epilogue overlaps refill
            NB_ARRIVE(3 + buf);

            // epilogue: cbias + FiLM (smem gamma/beta) + relu
            #pragma unroll
            for (int mi = 0; mi < 2; mi++) {
                #pragma unroll
                for (int h = 0; h < 2; h++) {
                    int eloc = cw * 32 + mi * 16 + gid + h * 8;
                    int e = e0 + eloc;
                    if (e < E) {
                        int bb;
                        if (bid64) bb = (int)((const long long*)bids)[e];
                        else       bb = ((const int*)bids)[e];
                        const float* gb = &SGB[bb * GB_STRIDE];
                        #pragma unroll
                        for (int nj = 0; nj < 8; nj++) {
                            int col = nj * 8 + tg * 2;
                            float2 ga = *(const float2*)&gb[col];
                            float2 be = *(const float2*)&gb[64 + col];
                            float x0 = acc[mi][nj][h * 2 + 0] + cb[nj].x;
                            float x1 = acc[mi][nj][h * 2 + 1] + cb[nj].y;
                            float2 o;
                            o.x = fmaxf(fmaf(x0, ga.x, be.x), 0.f);
                            o.y = fmaxf(fmaf(x1, ga.y, be.y), 0.f);
                            *(float2*)&out[(size_t)e * 64 + col] = o;
                        }
                    }
                }
            }
        }
    }
}

// ---------------------------------------------------------------------------
extern "C" void kernel_launch(void* const* d_in, const int* in_sizes, int n_in,
                              void* d_out, int out_size) {
    const float* nf   = (const float*)d_in[0];
    const void*  ei   = d_in[1];
    const float* eg   = (const float*)d_in[2];
    const float* cond = (const float*)d_in[3];
    const void*  bids = d_in[4];
    const float* Wn   = (const float*)d_in[5];
    const float* bn   = (const float*)d_in[6];
    const float* Wg   = (const float*)d_in[7];
    const float* bg   = (const float*)d_in[8];
    const float* Wc   = (const float*)d_in[9];
    const float* bc   = (const float*)d_in[10];
    const float* Wx   = (const float*)d_in[11];
    float* out = (float*)d_out;

    int N = in_sizes[0] / NODE_DIM;
    int E = in_sizes[2] / GEO_DIM;
    int B = in_sizes[3] / COND_DIM;
    int ntiles = (E + EDGE_TILE - 1) / EDGE_TILE;

    static int smem_set = 0;
    if (!smem_set) {
        cudaFuncSetAttribute(edge_kernel,
                             cudaFuncAttributeMaxDynamicSharedMemorySize,
                             SM_TOTAL);
        smem_set = 1;
    }

    detect_kernel<<<1, 1024>>>(ei, bids, E);
    prep_kernel<<<B + (KPAD * EDGE_DIM + 255) / 256, 256>>>(cond, Wc, bc, Wg, bg, Wx, B);
    nproj_kernel<<<(N + 63) / 64, 256>>>(nf, Wn, bn, N);
    int grid = 296;
    if (grid > ntiles) grid = ntiles;
    edge_kernel<<<grid, 256, SM_TOTAL>>>(ei, bids, eg, out, E, ntiles);
}

// round 7
// speedup vs baseline: 2.2754x; 1.1719x over previous
#include <cuda_runtime.h>
#include <cuda_fp16.h>
#include <stdint.h>

// ---------------------------------------------------------------------------
// EdgeFeat, Round 6: cp.async-pipelined, all-warp fp16 MMA edge kernel.
//   n_proj = node_feats @ Wn + bn                    (fp32 scalar GEMM)
//   x      = [nproj[src]*nproj[dst], e_geo] @ Wcomb  (K=72, fp16 4xk16 + k8)
//   out    = relu((x + cbias) * gamma[bid] + beta[bid])
// ---------------------------------------------------------------------------

#define NODE_DIM 64
#define EDGE_DIM 64
#define GEO_DIM  8
#define GEO_OUT  32
#define COND_DIM 512
#define KTOT     72
#define KPAD     80
#define MAX_NODES  100000
#define MAX_EDGES  800000
#define MAX_GRAPHS 64

#define EDGE_TILE 128
#define RAW_STRIDE 68          // floats; 272B rows, 16B aligned
#define JH_STRIDE 88           // halfs; conflict-free frag LDS
#define WT_STRIDE 88           // halfs
#define GB_STRIDE 132          // floats

// smem byte offsets
#define RAW_BUF_B  (256 * RAW_STRIDE * 4)                 // 69632
#define SM_RAW_OFF 0
#define SM_J_OFF   (SM_RAW_OFF + 2 * RAW_BUF_B)           // 139264
#define SM_J_B     (EDGE_TILE * JH_STRIDE * 2)            // 22528
#define SM_W_OFF   (SM_J_OFF + SM_J_B)                    // 161792
#define SM_W_B     (64 * WT_STRIDE * 2)                   // 11264
#define SM_GB_OFF  (SM_W_OFF + SM_W_B)                    // 173056
#define SM_GB_B    (64 * GB_STRIDE * 4)                   // 33792
#define SM_GEO_OFF (SM_GB_OFF + SM_GB_B)                  // 206848
#define SM_GEO_B   (EDGE_TILE * GEO_DIM * 4)              // 4096 per buf
#define SM_IDX_OFF (SM_GEO_OFF + 2 * SM_GEO_B)            // 215040
#define SM_IDX_B   2048                                   // per buf (int64 max)
#define SM_BID_OFF (SM_IDX_OFF + 2 * SM_IDX_B)            // 219136
#define SM_BID_B   1024                                   // per buf, 3 bufs
#define SM_TOTAL   (SM_BID_OFF + 3 * SM_BID_B)            // 222208

__device__ float  g_nproj[MAX_NODES * NODE_DIM];
__device__ float  g_gamma_beta[MAX_GRAPHS * 2 * EDGE_DIM];
__device__ __half g_wcomb_h[KPAD * EDGE_DIM];   // [k][n]
__device__ float  g_cbias[EDGE_DIM];
__device__ int    g_ei_is64;
__device__ int    g_bid_is64;

struct __align__(8) Half4 { __half2 lo, hi; };

__device__ __forceinline__ void cpa16(void* smp, const void* g) {
    unsigned sa = (unsigned)__cvta_generic_to_shared(smp);
    asm volatile("cp.async.cg.shared.global [%0], [%1], 16;" :: "r"(sa), "l"(g) : "memory");
}
#define CP_COMMIT() asm volatile("cp.async.commit_group;" ::: "memory")
#define CP_WAIT0()  asm volatile("cp.async.wait_group 0;" ::: "memory")

// ---------------------------------------------------------------------------
// Dtype probe (int64 vs silently-int32 indices); values < 2^17.
// ---------------------------------------------------------------------------
__global__ void detect_kernel(const void* ei, const void* bids, int E) {
    __shared__ int bad_ei, bad_bid;
    if (threadIdx.x == 0) { bad_ei = 0; bad_bid = 0; }
    __syncthreads();
    const unsigned long long* p64 = (const unsigned long long*)ei;
    const unsigned long long* b64 = (const unsigned long long*)bids;
    const int samples = 2048;
    long long n_ei = E;
    long long st_e = n_ei / samples; if (st_e < 1) st_e = 1;
    for (int i = threadIdx.x; i < samples; i += blockDim.x) {
        long long idx = (long long)i * st_e;
        if (idx >= n_ei) break;
        if (p64[idx] >> 32) bad_ei = 1;
    }
    long long n_b = E / 2;
    long long st_b = n_b / samples; if (st_b < 1) st_b = 1;
    for (int i = threadIdx.x; i < samples; i += blockDim.x) {
        long long idx = (long long)i * st_b;
        if (idx >= n_b) break;
        if (b64[idx] >> 32) bad_bid = 1;
    }
    __syncthreads();
    if (threadIdx.x == 0) { g_ei_is64 = !bad_ei; g_bid_is64 = !bad_bid; }
}

// ---------------------------------------------------------------------------
// prep: FiLM table (blocks 0..B-1) + Wcomb(fp16)/cbias (blocks B..)
// ---------------------------------------------------------------------------
__global__ void prep_kernel(const float* __restrict__ cond,
                            const float* __restrict__ Wc,
                            const float* __restrict__ bc,
                            const float* __restrict__ Wg,
                            const float* __restrict__ bg,
                            const float* __restrict__ Wx,
                            int B) {
    if ((int)blockIdx.x < B) {
        __shared__ float part[2 * EDGE_DIM];
        int b = blockIdx.x;
        int j = threadIdx.x & 127;
        int h = threadIdx.x >> 7;
        const float* crow = cond + (size_t)b * COND_DIM + h * 256;
        float acc = 0.f;
        #pragma unroll 4
        for (int k = 0; k < 256; k++)
            acc += crow[k] * Wc[(size_t)(h * 256 + k) * (2 * EDGE_DIM) + j];
        if (h == 1) part[j] = acc;
        __syncthreads();
        if (h == 0) {
            acc += part[j] + bc[j];
            if (j < EDGE_DIM) acc += 1.0f;
            g_gamma_beta[b * (2 * EDGE_DIM) + j] = acc;
        }
    } else {
        int idx = ((int)blockIdx.x - B) * 256 + threadIdx.x;
        if (idx < KPAD * EDGE_DIM) {
            int k = idx >> 6, c = idx & 63;
            float v = 0.f;
            if (k < EDGE_DIM) {
                v = Wx[k * EDGE_DIM + c];
            } else if (k < KTOT) {
                int gk = k - EDGE_DIM;
                #pragma unroll
                for (int m = 0; m < GEO_OUT; m++)
                    v += Wg[gk * GEO_OUT + m] * Wx[(EDGE_DIM + m) * EDGE_DIM + c];
            }
            g_wcomb_h[idx] = __float2half_rn(v);
        }
        if ((int)blockIdx.x == B && threadIdx.x < EDGE_DIM) {
            int c = threadIdx.x;
            float v = 0.f;
            #pragma unroll
            for (int m = 0; m < GEO_OUT; m++)
                v += bg[m] * Wx[(EDGE_DIM + m) * EDGE_DIM + c];
            g_cbias[c] = v;
        }
    }
}

// ---------------------------------------------------------------------------
// n_proj (fp32 scalar)
// ---------------------------------------------------------------------------
__global__ __launch_bounds__(256) void nproj_kernel(const float* __restrict__ nf,
                                                    const float* __restrict__ Wn,
                                                    const float* __restrict__ bn,
                                                    int N) {
    __shared__ float A[NODE_DIM][68];
    __shared__ float W[NODE_DIM][68];
    int tid = threadIdx.x;
    int n0 = blockIdx.x * 64;

    for (int i = tid; i < 64 * 16; i += 256) {
        int k = i >> 4; int c4 = (i & 15) << 2;
        float4 w = *(const float4*)&Wn[k * 64 + c4];
        W[k][c4] = w.x; W[k][c4 + 1] = w.y; W[k][c4 + 2] = w.z; W[k][c4 + 3] = w.w;
    }
    {
        int m = tid >> 2, p = tid & 3;
        int n = n0 + m;
        if (n < N) {
            const float4* row = (const float4*)&nf[(size_t)n * 64];
            #pragma unroll
            for (int i = 0; i < 4; i++) {
                float4 a = row[p * 4 + i];
                int k = (p * 4 + i) * 4;
                A[k][m] = a.x; A[k + 1][m] = a.y; A[k + 2][m] = a.z; A[k + 3][m] = a.w;
            }
        } else {
            #pragma unroll
            for (int i = 0; i < 4; i++) {
                int k = (p * 4 + i) * 4;
                A[k][m] = 0.f; A[k + 1][m] = 0.f; A[k + 2][m] = 0.f; A[k + 3][m] = 0.f;
            }
        }
    }
    __syncthreads();

    int tx = tid & 15, ty = tid >> 4;
    int m0 = tx << 2, c0 = ty << 2;
    float acc[4][4] = {};
    #pragma unroll 8
    for (int k = 0; k < 64; k++) {
        float4 a = *(float4*)&A[k][m0];
        float4 b = *(float4*)&W[k][c0];
        float av[4] = {a.x, a.y, a.z, a.w};
        float bv[4] = {b.x, b.y, b.z, b.w};
        #pragma unroll
        for (int i = 0; i < 4; i++)
            #pragma unroll
            for (int j = 0; j < 4; j++)
                acc[i][j] = fmaf(av[i], bv[j], acc[i][j]);
    }
    float4 bb = *(const float4*)&bn[c0];
    #pragma unroll
    for (int i = 0; i < 4; i++) {
        int n = n0 + m0 + i;
        if (n < N) {
            float4 o;
            o.x = acc[i][0] + bb.x; o.y = acc[i][1] + bb.y;
            o.z = acc[i][2] + bb.z; o.w = acc[i][3] + bb.w;
            *(float4*)&g_nproj[(size_t)n * 64 + c0] = o;
        }
    }
}

// ---------------------------------------------------------------------------
// Edge kernel: persistent, cp.async 2-deep pipeline, all-warp phases.
// ---------------------------------------------------------------------------
__global__ __launch_bounds__(256, 1) void edge_kernel(const void* __restrict__ ei,
                                                      const void* __restrict__ bids,
                                                      const float* __restrict__ e_geo,
                                                      float* __restrict__ out,
                                                      int E, int ntiles) {
    extern __shared__ __align__(16) char sm[];
    float*  RAW = (float*)(sm + SM_RAW_OFF);
    __half* J   = (__half*)(sm + SM_J_OFF);
    __half* Wt  = (__half*)(sm + SM_W_OFF);
    float*  SGB = (float*)(sm + SM_GB_OFF);
    float*  GEO = (float*)(sm + SM_GEO_OFF);
    char*   IDX = sm + SM_IDX_OFF;
    char*   BID = sm + SM_BID_OFF;

    const int tid = threadIdx.x;
    const int lane = tid & 31;
    const int wid = tid >> 5;
    const int ei64 = g_ei_is64;
    const int bid64 = g_bid_is64;
    const int esz = ei64 ? 8 : 4;
    const int bsz = bid64 ? 8 : 4;

    // one-time staging: W^T [n][k], gamma/beta table
    for (int i = tid; i < KTOT * EDGE_DIM; i += 256) {
        int k = i / 64, n = i & 63;
        Wt[n * WT_STRIDE + k] = g_wcomb_h[k * 64 + n];
    }
    for (int i = tid; i < 64 * 2 * EDGE_DIM; i += 256) {
        int b = i >> 7, c = i & 127;
        SGB[b * GB_STRIDE + c] = g_gamma_beta[i];
    }
    __syncthreads();

    // ---- per-warp B-fragment preload (tile-invariant) ----
    const int gid = lane >> 2;
    const int tg = lane & 3;
    unsigned bfr[8][8];     // [nj][ks*2+r] for ks=0..3
    unsigned b8[8];
    #pragma unroll
    for (int nj = 0; nj < 8; nj++) {
        const __half* wr = Wt + (nj * 8 + gid) * WT_STRIDE;
        #pragma unroll
        for (int ks = 0; ks < 4; ks++) {
            bfr[nj][ks * 2 + 0] = *(const unsigned*)&wr[ks * 16 + tg * 2];
            bfr[nj][ks * 2 + 1] = *(const unsigned*)&wr[ks * 16 + 8 + tg * 2];
        }
        b8[nj] = *(const unsigned*)&wr[64 + tg * 2];
    }
    float2 cb[8];
    #pragma unroll
    for (int nj = 0; nj < 8; nj++)
        cb[nj] = *(const float2*)&g_cbias[nj * 8 + tg * 2];

    // ---- cp.async helpers ----
    auto copy_idx = [&](int tile, int buf) {
        int e0 = tile * EDGE_TILE;
        int nch = 8 * esz;          // chunks per half
        int epc = 16 / esz;         // entries per chunk
        char* dst = IDX + buf * SM_IDX_B;
        if (tid < nch) {
            if (e0 + tid * epc < E)
                cpa16(dst + tid * 16, (const char*)ei + (size_t)e0 * esz + tid * 16);
        } else if (tid >= 128 && tid - 128 < nch) {
            int t = tid - 128;
            if (e0 + t * epc < E)
                cpa16(dst + nch * 16 + t * 16,
                      (const char*)ei + ((size_t)E + e0) * esz + t * 16);
        }
    };
    auto copy_bid = [&](int tile, int buf) {
        int e0 = tile * EDGE_TILE;
        int nch = 8 * bsz;
        int epc = 16 / bsz;
        char* dst = BID + buf * SM_BID_B;
        if (tid >= 64 && tid - 64 < nch) {
            int t = tid - 64;
            if (e0 + t * epc < E)
                cpa16(dst + t * 16, (const char*)bids + (size_t)e0 * bsz + t * 16);
        }
    };
    auto copy_geo = [&](int tile, int buf) {
        int e0 = tile * EDGE_TILE;
        if (e0 + (tid >> 1) < E)
            cpa16((char*)(GEO + buf * (SM_GEO_B / 4)) + tid * 16,
                  (const char*)e_geo + (size_t)e0 * 32 + tid * 16);
    };
    auto gather_raw = [&](int tile, int rbuf, int ibuf) {
        int e0 = tile * EDGE_TILE;
        char* rb = (char*)(RAW) + rbuf * RAW_BUF_B;
        const char* idxb = IDX + ibuf * SM_IDX_B;
        #pragma unroll
        for (int j = 0; j < 16; j++) {
            int g = j * 256 + tid;
            int row = g >> 4, c = g & 15;
            int e = e0 + (row & 127);
            int idx = 0;
            if (e < E)
                idx = ei64 ? (int)((const long long*)idxb)[row]
                           : ((const int*)idxb)[row];
            cpa16(rb + row * (RAW_STRIDE * 4) + c * 16,
                  (const char*)g_nproj + (size_t)idx * 256 + c * 16);
        }
    };

    int tile = blockIdx.x;
    if (tile >= ntiles) return;
    const int stride = gridDim.x;

    // prologue
    copy_idx(tile, 0);
    copy_bid(tile, 0);
    CP_COMMIT();
    CP_WAIT0();
    __syncthreads();
    {
        gather_raw(tile, 0, 0);
        copy_geo(tile, 0);
        int t1 = tile + stride;
        if (t1 < ntiles) { copy_idx(t1, 1); copy_bid(t1, 1); }
        CP_COMMIT();
    }

    for (int i = 0; tile < ntiles; tile += stride, i++) {
        CP_WAIT0();
        __syncthreads();

        // issue next tile's gather + next-next prefetch
        {
            int t1 = tile + stride;
            int t2 = tile + 2 * stride;
            if (t1 < ntiles) {
                gather_raw(t1, (i + 1) & 1, (i + 1) & 1);
                copy_geo(t1, (i + 1) & 1);
            }
            if (t2 < ntiles) {
                copy_idx(t2, i & 1);
                copy_bid(t2, (i + 2) % 3);
            }
            CP_COMMIT();
        }

        // ---- product phase: RAW -> J (fp16) ----
        {
            const float* base = RAW + (i & 1) * (RAW_BUF_B / 4);
            int m = tid >> 1, h = tid & 1;
            const float* s = base + m * RAW_STRIDE + h * 32;
            const float* d = base + (128 + m) * RAW_STRIDE + h * 32;
            __half* jr = J + m * JH_STRIDE + h * 32;
            #pragma unroll
            for (int j = 0; j < 8; j++) {
                float4 a = *(const float4*)(s + 4 * j);
                float4 b = *(const float4*)(d + 4 * j);
                Half4 hv;
                hv.lo = __floats2half2_rn(a.x * b.x, a.y * b.y);
                hv.hi = __floats2half2_rn(a.z * b.z, a.w * b.w);
                *(Half4*)(jr + 4 * j) = hv;
            }
        }
        __syncthreads();

        // ---- MMA: warp wid -> rows wid*16..+15, all 64 cols ----
        int e0 = tile * EDGE_TILE;
        float acc[8][4];
        #pragma unroll
        for (int nj = 0; nj < 8; nj++)
            #pragma unroll
            for (int q = 0; q < 4; q++) acc[nj][q] = 0.f;

        const __half* jwarp = J + (wid * 16 + gid) * JH_STRIDE;
        #pragma unroll
        for (int ks = 0; ks < 4; ks++) {
            unsigned a0 = *(const unsigned*)&jwarp[ks * 16 + tg * 2];
            unsigned a1 = *(const unsigned*)&jwarp[8 * JH_STRIDE + ks * 16 + tg * 2];
            unsigned a2 = *(const unsigned*)&jwarp[ks * 16 + 8 + tg * 2];
            unsigned a3 = *(const unsigned*)&jwarp[8 * JH_STRIDE + ks * 16 + 8 + tg * 2];
            #pragma unroll
            for (int nj = 0; nj < 8; nj++) {
                asm volatile(
                    "mma.sync.aligned.m16n8k16.row.col.f32.f16.f16.f32 "
                    "{%0,%1,%2,%3}, {%4,%5,%6,%7}, {%8,%9}, {%0,%1,%2,%3};\n"
                    : "+f"(acc[nj][0]), "+f"(acc[nj][1]),
                      "+f"(acc[nj][2]), "+f"(acc[nj][3])
                    : "r"(a0), "r"(a1), "r"(a2), "r"(a3),
                      "r"(bfr[nj][ks * 2]), "r"(bfr[nj][ks * 2 + 1]));
            }
        }
        {   // geo k8 step
            const float* gw = GEO + (i & 1) * (SM_GEO_B / 4) + (wid * 16 + gid) * 8 + tg * 2;
            float2 v0 = *(const float2*)gw;
            float2 v1 = *(const float2*)(gw + 64);
            __half2 h0 = __floats2half2_rn(v0.x, v0.y);
            __half2 h1 = __floats2half2_rn(v1.x, v1.y);
            unsigned ag0 = *(unsigned*)&h0;
            unsigned ag1 = *(unsigned*)&h1;
            #pragma unroll
            for (int nj = 0; nj < 8; nj++) {
                asm volatile(
                    "mma.sync.aligned.m16n8k8.row.col.f32.f16.f16.f32 "
                    "{%0,%1,%2,%3}, {%4,%5}, {%6}, {%0,%1,%2,%3};\n"
                    : "+f"(acc[nj][0]), "+f"(acc[nj][1]),
                      "+f"(acc[nj][2]), "+f"(acc[nj][3])
                    : "r"(ag0), "r"(ag1), "r"(b8[nj]));
            }
        }

        // ---- epilogue: cbias + FiLM + relu ----
        {
            const char* bidb = BID + (i % 3) * SM_BID_B;
            #pragma unroll
            for (int h = 0; h < 2; h++) {
                int eloc = wid * 16 + gid + h * 8;
                int e = e0 + eloc;
                if (e < E) {
                    int bb = bid64 ? (int)((const long long*)bidb)[eloc]
                                   : ((const int*)bidb)[eloc];
                    const float* gb = &SGB[bb * GB_STRIDE];
                    #pragma unroll
                    for (int nj = 0; nj < 8; nj++) {
                        int col = nj * 8 + tg * 2;
                        float2 ga = *(const float2*)&gb[col];
                        float2 be = *(const float2*)&gb[64 + col];
                        float x0 = acc[nj][h * 2 + 0] + cb[nj].x;
                        float x1 = acc[nj][h * 2 + 1] + cb[nj].y;
                        float2 o;
                        o.x = fmaxf(fmaf(x0, ga.x, be.x), 0.f);
                        o.y = fmaxf(fmaf(x1, ga.y, be.y), 0.f);
                        *(float2*)&out[(size_t)e * 64 + col] = o;
                    }
                }
            }
        }
    }
}

// ---------------------------------------------------------------------------
extern "C" void kernel_launch(void* const* d_in, const int* in_sizes, int n_in,
                              void* d_out, int out_size) {
    const float* nf   = (const float*)d_in[0];
    const void*  ei   = d_in[1];
    const float* eg   = (const float*)d_in[2];
    const float* cond = (const float*)d_in[3];
    const void*  bids = d_in[4];
    const float* Wn   = (const float*)d_in[5];
    const float* bn   = (const float*)d_in[6];
    const float* Wg   = (const float*)d_in[7];
    const float* bg   = (const float*)d_in[8];
    const float* Wc   = (const float*)d_in[9];
    const float* bc   = (const float*)d_in[10];
    const float* Wx   = (const float*)d_in[11];
    float* out = (float*)d_out;

    int N = in_sizes[0] / NODE_DIM;
    int E = in_sizes[2] / GEO_DIM;
    int B = in_sizes[3] / COND_DIM;
    int ntiles = (E + EDGE_TILE - 1) / EDGE_TILE;

    static int smem_set = 0;
    if (!smem_set) {
        cudaFuncSetAttribute(edge_kernel,
                             cudaFuncAttributeMaxDynamicSharedMemorySize,
                             SM_TOTAL);
        smem_set = 1;
    }

    detect_kernel<<<1, 1024>>>(ei, bids, E);
    prep_kernel<<<B + (KPAD * EDGE_DIM + 255) / 256, 256>>>(cond, Wc, bc, Wg, bg, Wx, B);
    nproj_kernel<<<(N + 63) / 64, 256>>>(nf, Wn, bn, N);
    int grid = ntiles < 148 ? ntiles : 148;
    edge_kernel<<<grid, 256, SM_TOTAL>>>(ei, bids, eg, out, E, ntiles);
}

// round 8
// speedup vs baseline: 3.0073x; 1.3216x over previous
#include <cuda_runtime.h>
#include <cuda_fp16.h>
#include <stdint.h>

// ---------------------------------------------------------------------------
// EdgeFeat, Round 7: fp16 nproj, direct-from-RAW A-frags, 2 CTA/SM.
//   n_proj = node_feats @ Wn + bn            (fp32 compute, fp16 store)
//   x      = [nproj[src]*nproj[dst], e_geo] @ Wcomb   (fp16 4xk16 + k8)
//   out    = relu((x + cbias) * gamma[bid] + beta[bid])
// ---------------------------------------------------------------------------

#define NODE_DIM 64
#define EDGE_DIM 64
#define GEO_DIM  8
#define GEO_OUT  32
#define COND_DIM 512
#define KTOT     72
#define KPAD     80
#define MAX_NODES  100000
#define MAX_EDGES  800000
#define MAX_GRAPHS 64

#define EDGE_TILE 128
#define WT_STRIDE 88           // halfs; 12*gid distinct mod 32 -> conflict-free
#define GB_STRIDE 132          // halfs

// smem layout (bytes). RAW rows: 128B fp16, XOR-swizzled 16B chunks, no pad.
#define RAW_BUF_B  (256 * 128)                            // 32768
#define SM_RAW_OFF 0
#define SM_IDX_OFF (2 * RAW_BUF_B)                        // 65536
#define SM_IDX_B   2048                                   // per buf (int64 max)
#define SM_W_OFF   (SM_IDX_OFF + 2 * SM_IDX_B)            // 69632
#define SM_W_B     (64 * WT_STRIDE * 2)                   // 11264
#define SM_GB_OFF  (SM_W_OFF + SM_W_B)                    // 80896
#define SM_GB_B    (64 * GB_STRIDE * 2)                   // 16896
#define SM_TOTAL   (SM_GB_OFF + SM_GB_B)                  // 97792

__device__ __half g_nproj_h[MAX_NODES * NODE_DIM];
__device__ float  g_gamma_beta[MAX_GRAPHS * 2 * EDGE_DIM];
__device__ __half g_wcomb_h[KPAD * EDGE_DIM];   // [k][n]
__device__ float  g_cbias[EDGE_DIM];
__device__ int    g_ei_is64;
__device__ int    g_bid_is64;

__device__ __forceinline__ void cpa16(void* smp, const void* g) {
    unsigned sa = (unsigned)__cvta_generic_to_shared(smp);
    asm volatile("cp.async.cg.shared.global [%0], [%1], 16;" :: "r"(sa), "l"(g) : "memory");
}
#define CP_COMMIT() asm volatile("cp.async.commit_group;" ::: "memory")
#define CP_WAIT0()  asm volatile("cp.async.wait_group 0;" ::: "memory")

// ---------------------------------------------------------------------------
// Dtype probe (int64 vs silently-int32 indices); values < 2^17.
// ---------------------------------------------------------------------------
__global__ void detect_kernel(const void* ei, const void* bids, int E) {
    __shared__ int bad_ei, bad_bid;
    if (threadIdx.x == 0) { bad_ei = 0; bad_bid = 0; }
    __syncthreads();
    const unsigned long long* p64 = (const unsigned long long*)ei;
    const unsigned long long* b64 = (const unsigned long long*)bids;
    const int samples = 2048;
    long long n_ei = E;
    long long st_e = n_ei / samples; if (st_e < 1) st_e = 1;
    for (int i = threadIdx.x; i < samples; i += blockDim.x) {
        long long idx = (long long)i * st_e;
        if (idx >= n_ei) break;
        if (p64[idx] >> 32) bad_ei = 1;
    }
    long long n_b = E / 2;
    long long st_b = n_b / samples; if (st_b < 1) st_b = 1;
    for (int i = threadIdx.x; i < samples; i += blockDim.x) {
        long long idx = (long long)i * st_b;
        if (idx >= n_b) break;
        if (b64[idx] >> 32) bad_bid = 1;
    }
    __syncthreads();
    if (threadIdx.x == 0) { g_ei_is64 = !bad_ei; g_bid_is64 = !bad_bid; }
}

// ---------------------------------------------------------------------------
// prep: FiLM table (blocks 0..B-1) + Wcomb(fp16)/cbias (blocks B..)
// ---------------------------------------------------------------------------
__global__ void prep_kernel(const float* __restrict__ cond,
                            const float* __restrict__ Wc,
                            const float* __restrict__ bc,
                            const float* __restrict__ Wg,
                            const float* __restrict__ bg,
                            const float* __restrict__ Wx,
                            int B) {
    if ((int)blockIdx.x < B) {
        __shared__ float part[2 * EDGE_DIM];
        int b = blockIdx.x;
        int j = threadIdx.x & 127;
        int h = threadIdx.x >> 7;
        const float* crow = cond + (size_t)b * COND_DIM + h * 256;
        float acc = 0.f;
        #pragma unroll 4
        for (int k = 0; k < 256; k++)
            acc += crow[k] * Wc[(size_t)(h * 256 + k) * (2 * EDGE_DIM) + j];
        if (h == 1) part[j] = acc;
        __syncthreads();
        if (h == 0) {
            acc += part[j] + bc[j];
            if (j < EDGE_DIM) acc += 1.0f;
            g_gamma_beta[b * (2 * EDGE_DIM) + j] = acc;
        }
    } else {
        int idx = ((int)blockIdx.x - B) * 256 + threadIdx.x;
        if (idx < KPAD * EDGE_DIM) {
            int k = idx >> 6, c = idx & 63;
            float v = 0.f;
            if (k < EDGE_DIM) {
                v = Wx[k * EDGE_DIM + c];
            } else if (k < KTOT) {
                int gk = k - EDGE_DIM;
                #pragma unroll
                for (int m = 0; m < GEO_OUT; m++)
                    v += Wg[gk * GEO_OUT + m] * Wx[(EDGE_DIM + m) * EDGE_DIM + c];
            }
            g_wcomb_h[idx] = __float2half_rn(v);
        }
        if ((int)blockIdx.x == B && threadIdx.x < EDGE_DIM) {
            int c = threadIdx.x;
            float v = 0.f;
            #pragma unroll
            for (int m = 0; m < GEO_OUT; m++)
                v += bg[m] * Wx[(EDGE_DIM + m) * EDGE_DIM + c];
            g_cbias[c] = v;
        }
    }
}

// ---------------------------------------------------------------------------
// n_proj: fp32 compute, fp16 store
// ---------------------------------------------------------------------------
__global__ __launch_bounds__(256) void nproj_kernel(const float* __restrict__ nf,
                                                    const float* __restrict__ Wn,
                                                    const float* __restrict__ bn,
                                                    int N) {
    __shared__ float A[NODE_DIM][68];
    __shared__ float W[NODE_DIM][68];
    int tid = threadIdx.x;
    int n0 = blockIdx.x * 64;

    for (int i = tid; i < 64 * 16; i += 256) {
        int k = i >> 4; int c4 = (i & 15) << 2;
        float4 w = *(const float4*)&Wn[k * 64 + c4];
        W[k][c4] = w.x; W[k][c4 + 1] = w.y; W[k][c4 + 2] = w.z; W[k][c4 + 3] = w.w;
    }
    {
        int m = tid >> 2, p = tid & 3;
        int n = n0 + m;
        if (n < N) {
            const float4* row = (const float4*)&nf[(size_t)n * 64];
            #pragma unroll
            for (int i = 0; i < 4; i++) {
                float4 a = row[p * 4 + i];
                int k = (p * 4 + i) * 4;
                A[k][m] = a.x; A[k + 1][m] = a.y; A[k + 2][m] = a.z; A[k + 3][m] = a.w;
            }
        } else {
            #pragma unroll
            for (int i = 0; i < 4; i++) {
                int k = (p * 4 + i) * 4;
                A[k][m] = 0.f; A[k + 1][m] = 0.f; A[k + 2][m] = 0.f; A[k + 3][m] = 0.f;
            }
        }
    }
    __syncthreads();

    int tx = tid & 15, ty = tid >> 4;
    int m0 = tx << 2, c0 = ty << 2;
    float acc[4][4] = {};
    #pragma unroll 8
    for (int k = 0; k < 64; k++) {
        float4 a = *(float4*)&A[k][m0];
        float4 b = *(float4*)&W[k][c0];
        float av[4] = {a.x, a.y, a.z, a.w};
        float bv[4] = {b.x, b.y, b.z, b.w};
        #pragma unroll
        for (int i = 0; i < 4; i++)
            #pragma unroll
            for (int j = 0; j < 4; j++)
                acc[i][j] = fmaf(av[i], bv[j], acc[i][j]);
    }
    float4 bb = *(const float4*)&bn[c0];
    #pragma unroll
    for (int i = 0; i < 4; i++) {
        int n = n0 + m0 + i;
        if (n < N) {
            __half2 h01 = __floats2half2_rn(acc[i][0] + bb.x, acc[i][1] + bb.y);
            __half2 h23 = __floats2half2_rn(acc[i][2] + bb.z, acc[i][3] + bb.w);
            uint2 st;
            st.x = *(unsigned*)&h01;
            st.y = *(unsigned*)&h23;
            *(uint2*)&g_nproj_h[(size_t)n * 64 + c0] = st;
        }
    }
}

// ---------------------------------------------------------------------------
// Edge kernel: persistent, cp.async pipeline, A-frags direct from swizzled
// fp16 RAW (XOR-swizzle on 16B chunks: chunk' = chunk ^ (row & 7)).
// ---------------------------------------------------------------------------
__global__ __launch_bounds__(256, 2) void edge_kernel(const void* __restrict__ ei,
                                                      const void* __restrict__ bids,
                                                      const float* __restrict__ e_geo,
                                                      float* __restrict__ out,
                                                      int E, int ntiles) {
    extern __shared__ __align__(16) char sm[];
    char*   RAW = sm + SM_RAW_OFF;
    char*   IDX = sm + SM_IDX_OFF;
    __half* Wt  = (__half*)(sm + SM_W_OFF);
    __half* GBs = (__half*)(sm + SM_GB_OFF);

    const int tid = threadIdx.x;
    const int lane = tid & 31;
    const int wid = tid >> 5;
    const int ei64 = g_ei_is64;
    const int bid64 = g_bid_is64;
    const int esz = ei64 ? 8 : 4;

    // one-time staging: W^T [n][k], gamma/beta (fp16)
    for (int i = tid; i < KTOT * EDGE_DIM; i += 256) {
        int k = i / 64, n = i & 63;
        Wt[n * WT_STRIDE + k] = g_wcomb_h[k * 64 + n];
    }
    for (int i = tid; i < 64 * 2 * EDGE_DIM; i += 256) {
        int b = i >> 7, c = i & 127;
        GBs[b * GB_STRIDE + c] = __float2half_rn(g_gamma_beta[i]);
    }
    __syncthreads();

    const int gid = lane >> 2;
    const int tg = lane & 3;

    // partial B hoist: ks 0,1 (k 0..31) + geo k8; ks 2,3 read from Wt.
    unsigned bfr[8][4];
    unsigned b8[8];
    #pragma unroll
    for (int nj = 0; nj < 8; nj++) {
        const __half* wr = Wt + (nj * 8 + gid) * WT_STRIDE;
        #pragma unroll
        for (int ks = 0; ks < 2; ks++) {
            bfr[nj][ks * 2 + 0] = *(const unsigned*)&wr[ks * 16 + tg * 2];
            bfr[nj][ks * 2 + 1] = *(const unsigned*)&wr[ks * 16 + 8 + tg * 2];
        }
        b8[nj] = *(const unsigned*)&wr[64 + tg * 2];
    }
    float2 cb[8];
    #pragma unroll
    for (int nj = 0; nj < 8; nj++)
        cb[nj] = *(const float2*)&g_cbias[nj * 8 + tg * 2];

    // per-thread A-frag smem offsets (xor index = gid, constant)
    const int roff_s  = (wid * 16 + gid) * 128 + tg * 4;
    const int roff_s8 = roff_s + 8 * 128;
    const int roff_d  = roff_s + 128 * 128;
    const int roff_d8 = roff_d + 8 * 128;

    auto copy_idx = [&](int tile, int buf) {
        int e0 = tile * EDGE_TILE;
        int nch = 8 * esz;          // 16B chunks per half (64 or 32)
        int epc = 16 / esz;
        char* dst = IDX + buf * SM_IDX_B;
        if (tid < nch) {
            if (e0 + tid * epc < E)
                cpa16(dst + tid * 16, (const char*)ei + (size_t)e0 * esz + tid * 16);
        } else if (tid >= 128 && tid - 128 < nch) {
            int t = tid - 128;
            if (e0 + t * epc < E)
                cpa16(dst + nch * 16 + t * 16,
                      (const char*)ei + ((size_t)E + e0) * esz + t * 16);
        }
    };
    auto gather_raw = [&](int tile, int rbuf, int ibuf) {
        int e0 = tile * EDGE_TILE;
        char* rb = RAW + rbuf * RAW_BUF_B;
        const char* idxb = IDX + ibuf * SM_IDX_B;
        #pragma unroll
        for (int j = 0; j < 8; j++) {
            int g = j * 256 + tid;
            int row = g >> 3, c = g & 7;
            int e = e0 + (row & 127);
            int idx = 0;
            if (e < E)
                idx = ei64 ? (int)((const long long*)idxb)[row]
                           : ((const int*)idxb)[row];
            cpa16(rb + row * 128 + ((c ^ (row & 7)) * 16),
                  (const char*)g_nproj_h + (size_t)idx * 128 + c * 16);
        }
    };

    int tile = blockIdx.x;
    if (tile >= ntiles) return;
    const int stride = gridDim.x;

    // prologue
    copy_idx(tile, 0);
    CP_COMMIT();
    CP_WAIT0();
    __syncthreads();
    gather_raw(tile, 0, 0);
    { int t1 = tile + stride; if (t1 < ntiles) copy_idx(t1, 1); }
    CP_COMMIT();

    for (int i = 0; tile < ntiles; tile += stride, i++) {
        CP_WAIT0();
        __syncthreads();

        {   // next tile gather + next-next idx prefetch
            int t1 = tile + stride;
            int t2 = tile + 2 * stride;
            if (t1 < ntiles) gather_raw(t1, (i + 1) & 1, (i + 1) & 1);
            if (t2 < ntiles) copy_idx(t2, i & 1);
            CP_COMMIT();
        }

        const char* rbase = RAW + (i & 1) * RAW_BUF_B;
        int e0 = tile * EDGE_TILE;

        // geo LDGs early (hidden behind k16 MMAs)
        int e1 = e0 + wid * 16 + gid;
        int e2 = e1 + 8;
        float2 gv0 = make_float2(0.f, 0.f), gv1 = make_float2(0.f, 0.f);
        if (e1 < E) gv0 = *(const float2*)&e_geo[(size_t)e1 * GEO_DIM + tg * 2];
        if (e2 < E) gv1 = *(const float2*)&e_geo[(size_t)e2 * GEO_DIM + tg * 2];

        float acc[8][4];
        #pragma unroll
        for (int nj = 0; nj < 8; nj++)
            #pragma unroll
            for (int q = 0; q < 4; q++) acc[nj][q] = 0.f;

        #pragma unroll
        for (int ks = 0; ks < 4; ks++) {
            int co0 = ((2 * ks) ^ gid) * 16;
            int co1 = ((2 * ks + 1) ^ gid) * 16;
            __half2 s0 = *(const __half2*)(rbase + roff_s  + co0);
            __half2 s1 = *(const __half2*)(rbase + roff_s8 + co0);
            __half2 s2 = *(const __half2*)(rbase + roff_s  + co1);
            __half2 s3 = *(const __half2*)(rbase + roff_s8 + co1);
            __half2 d0 = *(const __half2*)(rbase + roff_d  + co0);
            __half2 d1 = *(const __half2*)(rbase + roff_d8 + co0);
            __half2 d2 = *(const __half2*)(rbase + roff_d  + co1);
            __half2 d3 = *(const __half2*)(rbase + roff_d8 + co1);
            __half2 p0 = __hmul2(s0, d0);
            __half2 p1 = __hmul2(s1, d1);
            __half2 p2 = __hmul2(s2, d2);
            __half2 p3 = __hmul2(s3, d3);
            unsigned a0 = *(unsigned*)&p0;
            unsigned a1 = *(unsigned*)&p1;
            unsigned a2 = *(unsigned*)&p2;
            unsigned a3 = *(unsigned*)&p3;
            #pragma unroll
            for (int nj = 0; nj < 8; nj++) {
                unsigned bb0, bb1;
                if (ks < 2) {
                    bb0 = bfr[nj][ks * 2];
                    bb1 = bfr[nj][ks * 2 + 1];
                } else {
                    const __half* wr = Wt + (nj * 8 + gid) * WT_STRIDE + ks * 16;
                    bb0 = *(const unsigned*)&wr[tg * 2];
                    bb1 = *(const unsigned*)&wr[8 + tg * 2];
                }
                asm volatile(
                    "mma.sync.aligned.m16n8k16.row.col.f32.f16.f16.f32 "
                    "{%0,%1,%2,%3}, {%4,%5,%6,%7}, {%8,%9}, {%0,%1,%2,%3};\n"
                    : "+f"(acc[nj][0]), "+f"(acc[nj][1]),
                      "+f"(acc[nj][2]), "+f"(acc[nj][3])
                    : "r"(a0), "r"(a1), "r"(a2), "r"(a3),
                      "r"(bb0), "r"(bb1));
            }
        }
        {   // geo k8
            __half2 h0 = __floats2half2_rn(gv0.x, gv0.y);
            __half2 h1 = __floats2half2_rn(gv1.x, gv1.y);
            unsigned ag0 = *(unsigned*)&h0;
            unsigned ag1 = *(unsigned*)&h1;
            #pragma unroll
            for (int nj = 0; nj < 8; nj++) {
                asm volatile(
                    "mma.sync.aligned.m16n8k8.row.col.f32.f16.f16.f32 "
                    "{%0,%1,%2,%3}, {%4,%5}, {%6}, {%0,%1,%2,%3};\n"
                    : "+f"(acc[nj][0]), "+f"(acc[nj][1]),
                      "+f"(acc[nj][2]), "+f"(acc[nj][3])
                    : "r"(ag0), "r"(ag1), "r"(b8[nj]));
            }
        }

        // epilogue: cbias + FiLM (fp16 smem) + relu
        #pragma unroll
        for (int h = 0; h < 2; h++) {
            int e = e0 + wid * 16 + gid + h * 8;
            if (e < E) {
                int bb = bid64 ? (int)((const long long*)bids)[e]
                               : ((const int*)bids)[e];
                const __half* gb = GBs + bb * GB_STRIDE;
                #pragma unroll
                for (int nj = 0; nj < 8; nj++) {
                    int col = nj * 8 + tg * 2;
                    float2 ga = __half22float2(*(const __half2*)&gb[col]);
                    float2 be = __half22float2(*(const __half2*)&gb[64 + col]);
                    float x0 = acc[nj][h * 2 + 0] + cb[nj].x;
                    float x1 = acc[nj][h * 2 + 1] + cb[nj].y;
                    float2 o;
                    o.x = fmaxf(fmaf(x0, ga.x, be.x), 0.f);
                    o.y = fmaxf(fmaf(x1, ga.y, be.y), 0.f);
                    *(float2*)&out[(size_t)e * 64 + col] = o;
                }
            }
        }
    }
}

// ---------------------------------------------------------------------------
extern "C" void kernel_launch(void* const* d_in, const int* in_sizes, int n_in,
                              void* d_out, int out_size) {
    const float* nf   = (const float*)d_in[0];
    const void*  ei   = d_in[1];
    const float* eg   = (const float*)d_in[2];
    const float* cond = (const float*)d_in[3];
    const void*  bids = d_in[4];
    const float* Wn   = (const float*)d_in[5];
    const float* bn   = (const float*)d_in[6];
    const float* Wg   = (const float*)d_in[7];
    const float* bg   = (const float*)d_in[8];
    const float* Wc   = (const float*)d_in[9];
    const float* bc   = (const float*)d_in[10];
    const float* Wx   = (const float*)d_in[11];
    float* out = (float*)d_out;

    int N = in_sizes[0] / NODE_DIM;
    int E = in_sizes[2] / GEO_DIM;
    int B = in_sizes[3] / COND_DIM;
    int ntiles = (E + EDGE_TILE - 1) / EDGE_TILE;

    static int smem_set = 0;
    if (!smem_set) {
        cudaFuncSetAttribute(edge_kernel,
                             cudaFuncAttributeMaxDynamicSharedMemorySize,
                             SM_TOTAL);
        smem_set = 1;
    }

    detect_kernel<<<1, 1024>>>(ei, bids, E);
    prep_kernel<<<B + (KPAD * EDGE_DIM + 255) / 256, 256>>>(cond, Wc, bc, Wg, bg, Wx, B);
    nproj_kernel<<<(N + 63) / 64, 256>>>(nf, Wn, bn, N);
    int grid = 296;
    if (grid > ntiles) grid = ntiles;
    edge_kernel<<<grid, 256, SM_TOTAL>>>(ei, bids, eg, out, E, ntiles);
}

// round 11
// speedup vs baseline: 3.3059x; 1.0993x over previous
#include <cuda_runtime.h>
#include <cuda_fp16.h>
#include <stdint.h>

// ---------------------------------------------------------------------------
// EdgeFeat, Round 10 (= Round 9 resubmit after infra failure):
// fp16-MMA nproj (sigma-permuted store), edge epilogue staged through the
// (dead) current RAW buffer, GB stride fixed (132 halfs).
// ---------------------------------------------------------------------------

#define NODE_DIM 64
#define EDGE_DIM 64
#define GEO_DIM  8
#define GEO_OUT  32
#define COND_DIM 512
#define KTOT     72
#define KPAD     80
#define MAX_NODES  100000
#define MAX_EDGES  800000
#define MAX_GRAPHS 64

#define EDGE_TILE 128
#define WT_STRIDE 88           // halfs
#define GB_STRIDE 132          // halfs (128 data + 4 pad; 66 words ≡ 2 mod 32)
#define SOUT_STRIDE 72         // floats

// edge smem layout (bytes)
#define RAW_BUF_B  (256 * 128)                            // 32768
#define SM_RAW_OFF 0
#define SM_IDX_OFF (2 * RAW_BUF_B)                        // 65536
#define SM_IDX_B   2048
#define SM_W_OFF   (SM_IDX_OFF + 2 * SM_IDX_B)            // 69632
#define SM_W_B     (64 * WT_STRIDE * 2)                   // 11264
#define SM_GB_OFF  (SM_W_OFF + SM_W_B)                    // 80896
#define SM_GB_B    (64 * GB_STRIDE * 2)                   // 16896
#define SM_TOTAL   (SM_GB_OFF + SM_GB_B)                  // 97792

__device__ __half g_nproj_h[MAX_NODES * NODE_DIM];
__device__ float  g_gamma_beta[MAX_GRAPHS * 2 * EDGE_DIM];
__device__ __half g_wcomb_h[KPAD * EDGE_DIM];   // [k][n], rows k<64 sigma-permuted
__device__ float  g_cbias[EDGE_DIM];
__device__ int    g_ei_is64;
__device__ int    g_bid_is64;

struct __align__(8) Half4 { __half2 lo, hi; };

__device__ __forceinline__ void cpa16(void* smp, const void* g) {
    unsigned sa = (unsigned)__cvta_generic_to_shared(smp);
    asm volatile("cp.async.cg.shared.global [%0], [%1], 16;" :: "r"(sa), "l"(g) : "memory");
}
#define CP_COMMIT() asm volatile("cp.async.commit_group;" ::: "memory")
#define CP_WAIT0()  asm volatile("cp.async.wait_group 0;" ::: "memory")

__host__ __device__ __forceinline__ int sigma64(int c) {
    return ((c >> 1) & 7) * 8 + ((c >> 4) & 3) * 2 + (c & 1);
}

// ---------------------------------------------------------------------------
// prep: FiLM (blocks 0..B-1) + Wcomb/cbias (B..B+19) + dtype detect (B+20)
// ---------------------------------------------------------------------------
#define WCOMB_BLOCKS 20
__global__ void prep_kernel(const float* __restrict__ cond,
                            const float* __restrict__ Wc,
                            const float* __restrict__ bc,
                            const float* __restrict__ Wg,
                            const float* __restrict__ bg,
                            const float* __restrict__ Wx,
                            const void* __restrict__ ei,
                            const void* __restrict__ bids,
                            int B, int E) {
    __shared__ float part[2 * EDGE_DIM];
    __shared__ int bad[2];
    int bx = blockIdx.x;
    if (bx < B) {
        int b = bx;
        int j = threadIdx.x & 127;
        int h = threadIdx.x >> 7;
        const float* crow = cond + (size_t)b * COND_DIM + h * 256;
        float acc = 0.f;
        #pragma unroll 4
        for (int k = 0; k < 256; k++)
            acc += crow[k] * Wc[(size_t)(h * 256 + k) * (2 * EDGE_DIM) + j];
        if (h == 1) part[j] = acc;
        __syncthreads();
        if (h == 0) {
            acc += part[j] + bc[j];
            if (j < EDGE_DIM) acc += 1.0f;
            g_gamma_beta[b * (2 * EDGE_DIM) + j] = acc;
        }
    } else if (bx < B + WCOMB_BLOCKS) {
        int idx = (bx - B) * 256 + threadIdx.x;
        if (idx < KPAD * EDGE_DIM) {
            int k = idx >> 6, c = idx & 63;
            float v = 0.f;
            if (k < EDGE_DIM) {
                v = Wx[sigma64(k) * EDGE_DIM + c];      // compensate nproj perm
            } else if (k < KTOT) {
                int gk = k - EDGE_DIM;
                #pragma unroll
                for (int m = 0; m < GEO_OUT; m++)
                    v += Wg[gk * GEO_OUT + m] * Wx[(EDGE_DIM + m) * EDGE_DIM + c];
            }
            g_wcomb_h[idx] = __float2half_rn(v);
        }
        if (bx == B && threadIdx.x < EDGE_DIM) {
            int c = threadIdx.x;
            float v = 0.f;
            #pragma unroll
            for (int m = 0; m < GEO_OUT; m++)
                v += bg[m] * Wx[(EDGE_DIM + m) * EDGE_DIM + c];
            g_cbias[c] = v;
        }
    } else {
        // dtype probe: values < 2^17; nonzero high word => int32 packing
        if (threadIdx.x == 0) { bad[0] = 0; bad[1] = 0; }
        __syncthreads();
        const unsigned long long* p64 = (const unsigned long long*)ei;
        const unsigned long long* b64 = (const unsigned long long*)bids;
        const int samples = 2048;
        long long st_e = (long long)E / samples; if (st_e < 1) st_e = 1;
        for (int i = threadIdx.x; i < samples; i += blockDim.x) {
            long long idx = (long long)i * st_e;
            if (idx >= E) break;
            if (p64[idx] >> 32) bad[0] = 1;
        }
        long long n_b = E / 2;
        long long st_b = n_b / samples; if (st_b < 1) st_b = 1;
        for (int i = threadIdx.x; i < samples; i += blockDim.x) {
            long long idx = (long long)i * st_b;
            if (idx >= n_b) break;
            if (b64[idx] >> 32) bad[1] = 1;
        }
        __syncthreads();
        if (threadIdx.x == 0) { g_ei_is64 = !bad[0]; g_bid_is64 = !bad[1]; }
    }
}

// ---------------------------------------------------------------------------
// nproj: fp16 MMA, sigma-permuted fp16 store.
// ---------------------------------------------------------------------------
#define NW_STRIDE 72   // halfs
__global__ __launch_bounds__(256) void nproj_kernel(const float* __restrict__ nf,
                                                    const float* __restrict__ Wn,
                                                    const float* __restrict__ bn,
                                                    int N) {
    __shared__ __align__(16) __half As[128 * 64];
    __shared__ __align__(16) __half Ws[64 * NW_STRIDE];
    int tid = threadIdx.x;
    int lane = tid & 31;
    int wid = tid >> 5;
    int n0 = blockIdx.x * 128;

    for (int i = tid; i < 64 * 64; i += 256) {
        int k = i >> 6, n = i & 63;
        Ws[n * NW_STRIDE + k] = __float2half_rn(Wn[k * 64 + n]);
    }
    {
        int row = tid >> 1, h = tid & 1;
        int n = n0 + row;
        #pragma unroll
        for (int j = 0; j < 4; j++) {
            int c = h * 4 + j;
            int base = row * 64 + ((c ^ (row & 7)) * 8);
            if (n < N) {
                float4 a = *(const float4*)&nf[(size_t)n * 64 + c * 8];
                float4 b = *(const float4*)&nf[(size_t)n * 64 + c * 8 + 4];
                Half4 hv, hv2;
                hv.lo  = __floats2half2_rn(a.x, a.y);
                hv.hi  = __floats2half2_rn(a.z, a.w);
                hv2.lo = __floats2half2_rn(b.x, b.y);
                hv2.hi = __floats2half2_rn(b.z, b.w);
                *(Half4*)&As[base]     = hv;
                *(Half4*)&As[base + 4] = hv2;
            } else {
                Half4 hv;
                hv.lo = __float2half2_rn(0.f);
                hv.hi = __float2half2_rn(0.f);
                *(Half4*)&As[base]     = hv;
                *(Half4*)&As[base + 4] = hv;
            }
        }
    }
    __syncthreads();

    int gid = lane >> 2;
    int tg = lane & 3;
    float2 bnj[8];
    #pragma unroll
    for (int nj = 0; nj < 8; nj++)
        bnj[nj] = *(const float2*)&bn[nj * 8 + tg * 2];

    float acc[8][4];
    #pragma unroll
    for (int nj = 0; nj < 8; nj++)
        #pragma unroll
        for (int q = 0; q < 4; q++) acc[nj][q] = 0.f;

    const char* rbase = (const char*)As;
    const int roff  = (wid * 16 + gid) * 128 + tg * 4;
    const int roff8 = roff + 8 * 128;

    #pragma unroll
    for (int ks = 0; ks < 4; ks++) {
        int co0 = ((2 * ks) ^ gid) * 16;
        int co1 = ((2 * ks + 1) ^ gid) * 16;
        unsigned a0 = *(const unsigned*)(rbase + roff  + co0);
        unsigned a1 = *(const unsigned*)(rbase + roff8 + co0);
        unsigned a2 = *(const unsigned*)(rbase + roff  + co1);
        unsigned a3 = *(const unsigned*)(rbase + roff8 + co1);
        #pragma unroll
        for (int nj = 0; nj < 8; nj++) {
            const __half* wr = Ws + (nj * 8 + gid) * NW_STRIDE + ks * 16;
            unsigned bb0 = *(const unsigned*)&wr[tg * 2];
            unsigned bb1 = *(const unsigned*)&wr[8 + tg * 2];
            asm volatile(
                "mma.sync.aligned.m16n8k16.row.col.f32.f16.f16.f32 "
                "{%0,%1,%2,%3}, {%4,%5,%6,%7}, {%8,%9}, {%0,%1,%2,%3};\n"
                : "+f"(acc[nj][0]), "+f"(acc[nj][1]),
                  "+f"(acc[nj][2]), "+f"(acc[nj][3])
                : "r"(a0), "r"(a1), "r"(a2), "r"(a3), "r"(bb0), "r"(bb1));
        }
    }

    // permuted store: frag (nj,tg,b) -> stored col tg*16 + nj*2 + b
    #pragma unroll
    for (int h = 0; h < 2; h++) {
        int n = n0 + wid * 16 + gid + h * 8;
        if (n < N) {
            __half2 hp[8];
            #pragma unroll
            for (int nj = 0; nj < 8; nj++)
                hp[nj] = __floats2half2_rn(acc[nj][h * 2] + bnj[nj].x,
                                           acc[nj][h * 2 + 1] + bnj[nj].y);
            uint4 v0, v1;
            v0.x = *(unsigned*)&hp[0]; v0.y = *(unsigned*)&hp[1];
            v0.z = *(unsigned*)&hp[2]; v0.w = *(unsigned*)&hp[3];
            v1.x = *(unsigned*)&hp[4]; v1.y = *(unsigned*)&hp[5];
            v1.z = *(unsigned*)&hp[6]; v1.w = *(unsigned*)&hp[7];
            *(uint4*)&g_nproj_h[(size_t)n * 64 + tg * 16]     = v0;
            *(uint4*)&g_nproj_h[(size_t)n * 64 + tg * 16 + 8] = v1;
        }
    }
}

// ---------------------------------------------------------------------------
// Edge kernel: cp.async pipeline, direct-from-RAW A frags, epilogue staged
// through the dead current RAW buffer (freed after MMA frag loads).
// ---------------------------------------------------------------------------
__global__ __launch_bounds__(256, 2) void edge_kernel(const void* __restrict__ ei,
                                                      const void* __restrict__ bids,
                                                      const float* __restrict__ e_geo,
                                                      float* __restrict__ out,
                                                      int E, int ntiles) {
    extern __shared__ __align__(16) char sm[];
    char*   RAW  = sm + SM_RAW_OFF;
    char*   IDX  = sm + SM_IDX_OFF;
    __half* Wt   = (__half*)(sm + SM_W_OFF);
    __half* GBs  = (__half*)(sm + SM_GB_OFF);

    const int tid = threadIdx.x;
    const int lane = tid & 31;
    const int wid = tid >> 5;
    const int ei64 = g_ei_is64;
    const int bid64 = g_bid_is64;
    const int esz = ei64 ? 8 : 4;

    for (int i = tid; i < KTOT * EDGE_DIM; i += 256) {
        int k = i / 64, n = i & 63;
        Wt[n * WT_STRIDE + k] = g_wcomb_h[k * 64 + n];
    }
    for (int i = tid; i < 64 * 2 * EDGE_DIM; i += 256) {
        int b = i >> 7, c = i & 127;
        GBs[b * GB_STRIDE + c] = __float2half_rn(g_gamma_beta[i]);
    }
    __syncthreads();

    const int gid = lane >> 2;
    const int tg = lane & 3;

    unsigned bfr[8][4];
    unsigned b8[8];
    #pragma unroll
    for (int nj = 0; nj < 8; nj++) {
        const __half* wr = Wt + (nj * 8 + gid) * WT_STRIDE;
        #pragma unroll
        for (int ks = 0; ks < 2; ks++) {
            bfr[nj][ks * 2 + 0] = *(const unsigned*)&wr[ks * 16 + tg * 2];
            bfr[nj][ks * 2 + 1] = *(const unsigned*)&wr[ks * 16 + 8 + tg * 2];
        }
        b8[nj] = *(const unsigned*)&wr[64 + tg * 2];
    }
    float2 cb[8];
    #pragma unroll
    for (int nj = 0; nj < 8; nj++)
        cb[nj] = *(const float2*)&g_cbias[nj * 8 + tg * 2];

    const int roff_s  = (wid * 16 + gid) * 128 + tg * 4;
    const int roff_s8 = roff_s + 8 * 128;
    const int roff_d  = roff_s + 128 * 128;
    const int roff_d8 = roff_d + 8 * 128;

    auto copy_idx = [&](int tile, int buf) {
        int e0 = tile * EDGE_TILE;
        int nch = 8 * esz;
        int epc = 16 / esz;
        char* dst = IDX + buf * SM_IDX_B;
        if (tid < nch) {
            if (e0 + tid * epc < E)
                cpa16(dst + tid * 16, (const char*)ei + (size_t)e0 * esz + tid * 16);
        } else if (tid >= 128 && tid - 128 < nch) {
            int t = tid - 128;
            if (e0 + t * epc < E)
                cpa16(dst + nch * 16 + t * 16,
                      (const char*)ei + ((size_t)E + e0) * esz + t * 16);
        }
    };
    auto gather_raw = [&](int tile, int rbuf, int ibuf) {
        int e0 = tile * EDGE_TILE;
        char* rb = RAW + rbuf * RAW_BUF_B;
        const char* idxb = IDX + ibuf * SM_IDX_B;
        #pragma unroll
        for (int j = 0; j < 8; j++) {
            int g = j * 256 + tid;
            int row = g >> 3, c = g & 7;
            int e = e0 + (row & 127);
            int idx = 0;
            if (e < E)
                idx = ei64 ? (int)((const long long*)idxb)[row]
                           : ((const int*)idxb)[row];
            cpa16(rb + row * 128 + ((c ^ (row & 7)) * 16),
                  (const char*)g_nproj_h + (size_t)idx * 128 + c * 16);
        }
    };

    int tile = blockIdx.x;
    if (tile >= ntiles) return;
    const int stride = gridDim.x;

    copy_idx(tile, 0);
    CP_COMMIT();
    CP_WAIT0();
    __syncthreads();
    gather_raw(tile, 0, 0);
    { int t1 = tile + stride; if (t1 < ntiles) copy_idx(t1, 1); }
    CP_COMMIT();

    for (int i = 0; tile < ntiles; tile += stride, i++) {
        CP_WAIT0();
        __syncthreads();

        {
            int t1 = tile + stride;
            int t2 = tile + 2 * stride;
            if (t1 < ntiles) gather_raw(t1, (i + 1) & 1, (i + 1) & 1);
            if (t2 < ntiles) copy_idx(t2, i & 1);
            CP_COMMIT();
        }

        const char* rbase = RAW + (i & 1) * RAW_BUF_B;
        int e0 = tile * EDGE_TILE;

        int e1 = e0 + wid * 16 + gid;
        int e2 = e1 + 8;
        float2 gv0 = make_float2(0.f, 0.f), gv1 = make_float2(0.f, 0.f);
        if (e1 < E) gv0 = *(const float2*)&e_geo[(size_t)e1 * GEO_DIM + tg * 2];
        if (e2 < E) gv1 = *(const float2*)&e_geo[(size_t)e2 * GEO_DIM + tg * 2];

        float acc[8][4];
        #pragma unroll
        for (int nj = 0; nj < 8; nj++)
            #pragma unroll
            for (int q = 0; q < 4; q++) acc[nj][q] = 0.f;

        #pragma unroll
        for (int ks = 0; ks < 4; ks++) {
            int co0 = ((2 * ks) ^ gid) * 16;
            int co1 = ((2 * ks + 1) ^ gid) * 16;
            __half2 s0 = *(const __half2*)(rbase + roff_s  + co0);
            __half2 s1 = *(const __half2*)(rbase + roff_s8 + co0);
            __half2 s2 = *(const __half2*)(rbase + roff_s  + co1);
            __half2 s3 = *(const __half2*)(rbase + roff_s8 + co1);
            __half2 d0 = *(const __half2*)(rbase + roff_d  + co0);
            __half2 d1 = *(const __half2*)(rbase + roff_d8 + co0);
            __half2 d2 = *(const __half2*)(rbase + roff_d  + co1);
            __half2 d3 = *(const __half2*)(rbase + roff_d8 + co1);
            __half2 p0 = __hmul2(s0, d0);
            __half2 p1 = __hmul2(s1, d1);
            __half2 p2 = __hmul2(s2, d2);
            __half2 p3 = __hmul2(s3, d3);
            unsigned a0 = *(unsigned*)&p0;
            unsigned a1 = *(unsigned*)&p1;
            unsigned a2 = *(unsigned*)&p2;
            unsigned a3 = *(unsigned*)&p3;
            #pragma unroll
            for (int nj = 0; nj < 8; nj++) {
                unsigned bb0, bb1;
                if (ks < 2) {
                    bb0 = bfr[nj][ks * 2];
                    bb1 = bfr[nj][ks * 2 + 1];
                } else {
                    const __half* wr = Wt + (nj * 8 + gid) * WT_STRIDE + ks * 16;
                    bb0 = *(const unsigned*)&wr[tg * 2];
                    bb1 = *(const unsigned*)&wr[8 + tg * 2];
                }
                asm volatile(
                    "mma.sync.aligned.m16n8k16.row.col.f32.f16.f16.f32 "
                    "{%0,%1,%2,%3}, {%4,%5,%6,%7}, {%8,%9}, {%0,%1,%2,%3};\n"
                    : "+f"(acc[nj][0]), "+f"(acc[nj][1]),
                      "+f"(acc[nj][2]), "+f"(acc[nj][3])
                    : "r"(a0), "r"(a1), "r"(a2), "r"(a3),
                      "r"(bb0), "r"(bb1));
            }
        }
        {
            __half2 h0 = __floats2half2_rn(gv0.x, gv0.y);
            __half2 h1 = __floats2half2_rn(gv1.x, gv1.y);
            unsigned ag0 = *(unsigned*)&h0;
            unsigned ag1 = *(unsigned*)&h1;
            #pragma unroll
            for (int nj = 0; nj < 8; nj++) {
                asm volatile(
                    "mma.sync.aligned.m16n8k8.row.col.f32.f16.f16.f32 "
                    "{%0,%1,%2,%3}, {%4,%5}, {%6}, {%0,%1,%2,%3};\n"
                    : "+f"(acc[nj][0]), "+f"(acc[nj][1]),
                      "+f"(acc[nj][2]), "+f"(acc[nj][3])
                    : "r"(ag0), "r"(ag1), "r"(b8[nj]));
            }
        }

        // FiLM in place
        #pragma unroll
        for (int h = 0; h < 2; h++) {
            int e = e0 + wid * 16 + gid + h * 8;
            if (e < E) {
                int bb = bid64 ? (int)((const long long*)bids)[e]
                               : ((const int*)bids)[e];
                const __half* gb = GBs + bb * GB_STRIDE;
                #pragma unroll
                for (int nj = 0; nj < 8; nj++) {
                    int col = nj * 8 + tg * 2;
                    float2 ga = __half22float2(*(const __half2*)&gb[col]);
                    float2 be = __half22float2(*(const __half2*)&gb[64 + col]);
                    float x0 = acc[nj][h * 2 + 0] + cb[nj].x;
                    float x1 = acc[nj][h * 2 + 1] + cb[nj].y;
                    acc[nj][h * 2 + 0] = fmaxf(fmaf(x0, ga.x, be.x), 0.f);
                    acc[nj][h * 2 + 1] = fmaxf(fmaf(x1, ga.y, be.y), 0.f);
                }
            }
        }

        // epilogue staged through dead RAW buffer (all frag reads done)
        __syncthreads();
        float* SOUT = (float*)(RAW + (i & 1) * RAW_BUF_B);
        #pragma unroll
        for (int pass = 0; pass < 2; pass++) {
            if ((wid >> 2) == pass) {
                int wl = wid & 3;
                #pragma unroll
                for (int h = 0; h < 2; h++) {
                    int r = wl * 16 + gid + h * 8;       // local row 0..63
                    #pragma unroll
                    for (int nj = 0; nj < 8; nj++) {
                        float2 v;
                        v.x = acc[nj][h * 2 + 0];
                        v.y = acc[nj][h * 2 + 1];
                        *(float2*)&SOUT[r * SOUT_STRIDE + nj * 8 + tg * 2] = v;
                    }
                }
            }
            __syncthreads();
            int rb0 = pass * 64;
            #pragma unroll
            for (int it = 0; it < 4; it++) {
                int flat = it * 4096 + tid * 16;         // byte in 16KB half
                int r = flat >> 8;
                int cB = flat & 255;
                int e = e0 + rb0 + r;
                if (e < E) {
                    float4 v = *(const float4*)((const char*)SOUT +
                                                r * (SOUT_STRIDE * 4) + cB);
                    *(float4*)((char*)out + (size_t)e * 256 + cB) = v;
                }
            }
            __syncthreads();
        }
    }
}

// ---------------------------------------------------------------------------
extern "C" void kernel_launch(void* const* d_in, const int* in_sizes, int n_in,
                              void* d_out, int out_size) {
    const float* nf   = (const float*)d_in[0];
    const void*  ei   = d_in[1];
    const float* eg   = (const float*)d_in[2];
    const float* cond = (const float*)d_in[3];
    const void*  bids = d_in[4];
    const float* Wn   = (const float*)d_in[5];
    const float* bn   = (const float*)d_in[6];
    const float* Wg   = (const float*)d_in[7];
    const float* bg   = (const float*)d_in[8];
    const float* Wc   = (const float*)d_in[9];
    const float* bc   = (const float*)d_in[10];
    const float* Wx   = (const float*)d_in[11];
    float* out = (float*)d_out;

    int N = in_sizes[0] / NODE_DIM;
    int E = in_sizes[2] / GEO_DIM;
    int B = in_sizes[3] / COND_DIM;
    int ntiles = (E + EDGE_TILE - 1) / EDGE_TILE;

    static int smem_set = 0;
    if (!smem_set) {
        cudaFuncSetAttribute(edge_kernel,
                             cudaFuncAttributeMaxDynamicSharedMemorySize,
                             SM_TOTAL);
        smem_set = 1;
    }

    prep_kernel<<<B + WCOMB_BLOCKS + 1, 256>>>(cond, Wc, bc, Wg, bg, Wx,
                                               ei, bids, B, E);
    nproj_kernel<<<(N + 127) / 128, 256>>>(nf, Wn, bn, N);
    int grid = 296;
    if (grid > ntiles) grid = ntiles;
    edge_kernel<<<grid, 256, SM_TOTAL>>>(ei, bids, eg, out, E, ntiles);
}

// round 12
// speedup vs baseline: 3.7851x; 1.1449x over previous
#include <cuda_runtime.h>
#include <cuda_fp16.h>
#include <stdint.h>

// ---------------------------------------------------------------------------
// EdgeFeat, Round 11: prep fused into nproj launch (independent work,
// overlapped); FiLM inner loop rebuilt with 16-way MLP. Edge kernel
// unchanged from the 147.6us Round-10 winner.
// ---------------------------------------------------------------------------

#define NODE_DIM 64
#define EDGE_DIM 64
#define GEO_DIM  8
#define GEO_OUT  32
#define COND_DIM 512
#define KTOT     72
#define KPAD     80
#define MAX_NODES  100000
#define MAX_EDGES  800000
#define MAX_GRAPHS 64

#define EDGE_TILE 128
#define WT_STRIDE 88           // halfs
#define GB_STRIDE 132          // halfs (128 data + 4 pad)
#define SOUT_STRIDE 72         // floats

// edge smem layout (bytes)
#define RAW_BUF_B  (256 * 128)                            // 32768
#define SM_RAW_OFF 0
#define SM_IDX_OFF (2 * RAW_BUF_B)                        // 65536
#define SM_IDX_B   2048
#define SM_W_OFF   (SM_IDX_OFF + 2 * SM_IDX_B)            // 69632
#define SM_W_B     (64 * WT_STRIDE * 2)                   // 11264
#define SM_GB_OFF  (SM_W_OFF + SM_W_B)                    // 80896
#define SM_GB_B    (64 * GB_STRIDE * 2)                   // 16896
#define SM_TOTAL   (SM_GB_OFF + SM_GB_B)                  // 97792

__device__ __half g_nproj_h[MAX_NODES * NODE_DIM];
__device__ float  g_gamma_beta[MAX_GRAPHS * 2 * EDGE_DIM];
__device__ __half g_wcomb_h[KPAD * EDGE_DIM];   // [k][n], rows k<64 sigma-permuted
__device__ float  g_cbias[EDGE_DIM];
__device__ int    g_ei_is64;
__device__ int    g_bid_is64;

struct __align__(8) Half4 { __half2 lo, hi; };

__device__ __forceinline__ void cpa16(void* smp, const void* g) {
    unsigned sa = (unsigned)__cvta_generic_to_shared(smp);
    asm volatile("cp.async.cg.shared.global [%0], [%1], 16;" :: "r"(sa), "l"(g) : "memory");
}
#define CP_COMMIT() asm volatile("cp.async.commit_group;" ::: "memory")
#define CP_WAIT0()  asm volatile("cp.async.wait_group 0;" ::: "memory")

__host__ __device__ __forceinline__ int sigma64(int c) {
    return ((c >> 1) & 7) * 8 + ((c >> 4) & 3) * 2 + (c & 1);
}

#define WCOMB_BLOCKS 20
#define NW_STRIDE 72   // halfs

// ---------------------------------------------------------------------------
// Fused kernel: blocks [0,npb) = nproj fp16-MMA tiles (sigma-permuted store);
// blocks [npb, npb+B) = FiLM (MLP-16); then Wcomb/cbias; last = dtype detect.
// ---------------------------------------------------------------------------
__global__ __launch_bounds__(256) void fused_kernel(const float* __restrict__ nf,
                                                    const float* __restrict__ Wn,
                                                    const float* __restrict__ bn,
                                                    const float* __restrict__ cond,
                                                    const float* __restrict__ Wc,
                                                    const float* __restrict__ bc,
                                                    const float* __restrict__ Wg,
                                                    const float* __restrict__ bg,
                                                    const float* __restrict__ Wx,
                                                    const void* __restrict__ ei,
                                                    const void* __restrict__ bids,
                                                    int N, int B, int E, int npb) {
    int bx = blockIdx.x;
    int tid = threadIdx.x;

    if (bx < npb) {
        // ================= nproj tile =================
        __shared__ __align__(16) __half As[128 * 64];
        __shared__ __align__(16) __half Ws[64 * NW_STRIDE];
        int lane = tid & 31;
        int wid = tid >> 5;
        int n0 = bx * 128;

        for (int i = tid; i < 64 * 64; i += 256) {
            int k = i >> 6, n = i & 63;
            Ws[n * NW_STRIDE + k] = __float2half_rn(Wn[k * 64 + n]);
        }
        {
            int row = tid >> 1, h = tid & 1;
            int n = n0 + row;
            #pragma unroll
            for (int j = 0; j < 4; j++) {
                int c = h * 4 + j;
                int base = row * 64 + ((c ^ (row & 7)) * 8);
                if (n < N) {
                    float4 a = *(const float4*)&nf[(size_t)n * 64 + c * 8];
                    float4 b = *(const float4*)&nf[(size_t)n * 64 + c * 8 + 4];
                    Half4 hv, hv2;
                    hv.lo  = __floats2half2_rn(a.x, a.y);
                    hv.hi  = __floats2half2_rn(a.z, a.w);
                    hv2.lo = __floats2half2_rn(b.x, b.y);
                    hv2.hi = __floats2half2_rn(b.z, b.w);
                    *(Half4*)&As[base]     = hv;
                    *(Half4*)&As[base + 4] = hv2;
                } else {
                    Half4 hv;
                    hv.lo = __float2half2_rn(0.f);
                    hv.hi = __float2half2_rn(0.f);
                    *(Half4*)&As[base]     = hv;
                    *(Half4*)&As[base + 4] = hv;
                }
            }
        }
        __syncthreads();

        int gid = lane >> 2;
        int tg = lane & 3;
        float2 bnj[8];
        #pragma unroll
        for (int nj = 0; nj < 8; nj++)
            bnj[nj] = *(const float2*)&bn[nj * 8 + tg * 2];

        float acc[8][4];
        #pragma unroll
        for (int nj = 0; nj < 8; nj++)
            #pragma unroll
            for (int q = 0; q < 4; q++) acc[nj][q] = 0.f;

        const char* rbase = (const char*)As;
        const int roff  = (wid * 16 + gid) * 128 + tg * 4;
        const int roff8 = roff + 8 * 128;

        #pragma unroll
        for (int ks = 0; ks < 4; ks++) {
            int co0 = ((2 * ks) ^ gid) * 16;
            int co1 = ((2 * ks + 1) ^ gid) * 16;
            unsigned a0 = *(const unsigned*)(rbase + roff  + co0);
            unsigned a1 = *(const unsigned*)(rbase + roff8 + co0);
            unsigned a2 = *(const unsigned*)(rbase + roff  + co1);
            unsigned a3 = *(const unsigned*)(rbase + roff8 + co1);
            #pragma unroll
            for (int nj = 0; nj < 8; nj++) {
                const __half* wr = Ws + (nj * 8 + gid) * NW_STRIDE + ks * 16;
                unsigned bb0 = *(const unsigned*)&wr[tg * 2];
                unsigned bb1 = *(const unsigned*)&wr[8 + tg * 2];
                asm volatile(
                    "mma.sync.aligned.m16n8k16.row.col.f32.f16.f16.f32 "
                    "{%0,%1,%2,%3}, {%4,%5,%6,%7}, {%8,%9}, {%0,%1,%2,%3};\n"
                    : "+f"(acc[nj][0]), "+f"(acc[nj][1]),
                      "+f"(acc[nj][2]), "+f"(acc[nj][3])
                    : "r"(a0), "r"(a1), "r"(a2), "r"(a3), "r"(bb0), "r"(bb1));
            }
        }

        // permuted store: frag (nj,tg,b) -> stored col tg*16 + nj*2 + b
        #pragma unroll
        for (int h = 0; h < 2; h++) {
            int n = n0 + wid * 16 + gid + h * 8;
            if (n < N) {
                __half2 hp[8];
                #pragma unroll
                for (int nj = 0; nj < 8; nj++)
                    hp[nj] = __floats2half2_rn(acc[nj][h * 2] + bnj[nj].x,
                                               acc[nj][h * 2 + 1] + bnj[nj].y);
                uint4 v0, v1;
                v0.x = *(unsigned*)&hp[0]; v0.y = *(unsigned*)&hp[1];
                v0.z = *(unsigned*)&hp[2]; v0.w = *(unsigned*)&hp[3];
                v1.x = *(unsigned*)&hp[4]; v1.y = *(unsigned*)&hp[5];
                v1.z = *(unsigned*)&hp[6]; v1.w = *(unsigned*)&hp[7];
                *(uint4*)&g_nproj_h[(size_t)n * 64 + tg * 16]     = v0;
                *(uint4*)&g_nproj_h[(size_t)n * 64 + tg * 16 + 8] = v1;
            }
        }
        return;
    }

    int pb = bx - npb;
    if (pb < B) {
        // ================= FiLM, MLP-16 =================
        __shared__ float part[2 * EDGE_DIM];
        int b = pb;
        int j = tid & 127;
        int h = tid >> 7;
        const float* crow = cond + (size_t)b * COND_DIM + h * 256;
        const float* wcol = Wc + (size_t)h * 256 * (2 * EDGE_DIM) + j;
        float accs[16];
        #pragma unroll
        for (int u = 0; u < 16; u++) accs[u] = 0.f;
        for (int k0 = 0; k0 < 256; k0 += 16) {
            #pragma unroll
            for (int u = 0; u < 16; u++)
                accs[u] = fmaf(crow[k0 + u],
                               wcol[(size_t)(k0 + u) * (2 * EDGE_DIM)],
                               accs[u]);
        }
        #pragma unroll
        for (int s = 8; s > 0; s >>= 1)
            #pragma unroll
            for (int u = 0; u < 8; u++)
                if (u < s) accs[u] += accs[u + s];
        float acc = accs[0];
        if (h == 1) part[j] = acc;
        __syncthreads();
        if (h == 0) {
            acc += part[j] + bc[j];
            if (j < EDGE_DIM) acc += 1.0f;
            g_gamma_beta[b * (2 * EDGE_DIM) + j] = acc;
        }
    } else if (pb < B + WCOMB_BLOCKS) {
        int idx = (pb - B) * 256 + tid;
        if (idx < KPAD * EDGE_DIM) {
            int k = idx >> 6, c = idx & 63;
            float v = 0.f;
            if (k < EDGE_DIM) {
                v = Wx[sigma64(k) * EDGE_DIM + c];      // compensate nproj perm
            } else if (k < KTOT) {
                int gk = k - EDGE_DIM;
                #pragma unroll
                for (int m = 0; m < GEO_OUT; m++)
                    v += Wg[gk * GEO_OUT + m] * Wx[(EDGE_DIM + m) * EDGE_DIM + c];
            }
            g_wcomb_h[idx] = __float2half_rn(v);
        }
        if (pb == B && tid < EDGE_DIM) {
            int c = tid;
            float v = 0.f;
            #pragma unroll
            for (int m = 0; m < GEO_OUT; m++)
                v += bg[m] * Wx[(EDGE_DIM + m) * EDGE_DIM + c];
            g_cbias[c] = v;
        }
    } else {
        // dtype probe: values < 2^17; nonzero high word => int32 packing
        __shared__ int bad[2];
        if (tid == 0) { bad[0] = 0; bad[1] = 0; }
        __syncthreads();
        const unsigned long long* p64 = (const unsigned long long*)ei;
        const unsigned long long* b64 = (const unsigned long long*)bids;
        const int samples = 2048;
        long long st_e = (long long)E / samples; if (st_e < 1) st_e = 1;
        for (int i = tid; i < samples; i += blockDim.x) {
            long long idx = (long long)i * st_e;
            if (idx >= E) break;
            if (p64[idx] >> 32) bad[0] = 1;
        }
        long long n_b = E / 2;
        long long st_b = n_b / samples; if (st_b < 1) st_b = 1;
        for (int i = tid; i < samples; i += blockDim.x) {
            long long idx = (long long)i * st_b;
            if (idx >= n_b) break;
            if (b64[idx] >> 32) bad[1] = 1;
        }
        __syncthreads();
        if (tid == 0) { g_ei_is64 = !bad[0]; g_bid_is64 = !bad[1]; }
    }
}

// ---------------------------------------------------------------------------
// Edge kernel (unchanged from Round-10 147.6us winner).
// ---------------------------------------------------------------------------
__global__ __launch_bounds__(256, 2) void edge_kernel(const void* __restrict__ ei,
                                                      const void* __restrict__ bids,
                                                      const float* __restrict__ e_geo,
                                                      float* __restrict__ out,
                                                      int E, int ntiles) {
    extern __shared__ __align__(16) char sm[];
    char*   RAW  = sm + SM_RAW_OFF;
    char*   IDX  = sm + SM_IDX_OFF;
    __half* Wt   = (__half*)(sm + SM_W_OFF);
    __half* GBs  = (__half*)(sm + SM_GB_OFF);

    const int tid = threadIdx.x;
    const int lane = tid & 31;
    const int wid = tid >> 5;
    const int ei64 = g_ei_is64;
    const int bid64 = g_bid_is64;
    const int esz = ei64 ? 8 : 4;

    for (int i = tid; i < KTOT * EDGE_DIM; i += 256) {
        int k = i / 64, n = i & 63;
        Wt[n * WT_STRIDE + k] = g_wcomb_h[k * 64 + n];
    }
    for (int i = tid; i < 64 * 2 * EDGE_DIM; i += 256) {
        int b = i >> 7, c = i & 127;
        GBs[b * GB_STRIDE + c] = __float2half_rn(g_gamma_beta[i]);
    }
    __syncthreads();

    const int gid = lane >> 2;
    const int tg = lane & 3;

    unsigned bfr[8][4];
    unsigned b8[8];
    #pragma unroll
    for (int nj = 0; nj < 8; nj++) {
        const __half* wr = Wt + (nj * 8 + gid) * WT_STRIDE;
        #pragma unroll
        for (int ks = 0; ks < 2; ks++) {
            bfr[nj][ks * 2 + 0] = *(const unsigned*)&wr[ks * 16 + tg * 2];
            bfr[nj][ks * 2 + 1] = *(const unsigned*)&wr[ks * 16 + 8 + tg * 2];
        }
        b8[nj] = *(const unsigned*)&wr[64 + tg * 2];
    }
    float2 cb[8];
    #pragma unroll
    for (int nj = 0; nj < 8; nj++)
        cb[nj] = *(const float2*)&g_cbias[nj * 8 + tg * 2];

    const int roff_s  = (wid * 16 + gid) * 128 + tg * 4;
    const int roff_s8 = roff_s + 8 * 128;
    const int roff_d  = roff_s + 128 * 128;
    const int roff_d8 = roff_d + 8 * 128;

    auto copy_idx = [&](int tile, int buf) {
        int e0 = tile * EDGE_TILE;
        int nch = 8 * esz;
        int epc = 16 / esz;
        char* dst = IDX + buf * SM_IDX_B;
        if (tid < nch) {
            if (e0 + tid * epc < E)
                cpa16(dst + tid * 16, (const char*)ei + (size_t)e0 * esz + tid * 16);
        } else if (tid >= 128 && tid - 128 < nch) {
            int t = tid - 128;
            if (e0 + t * epc < E)
                cpa16(dst + nch * 16 + t * 16,
                      (const char*)ei + ((size_t)E + e0) * esz + t * 16);
        }
    };
    auto gather_raw = [&](int tile, int rbuf, int ibuf) {
        int e0 = tile * EDGE_TILE;
        char* rb = RAW + rbuf * RAW_BUF_B;
        const char* idxb = IDX + ibuf * SM_IDX_B;
        #pragma unroll
        for (int j = 0; j < 8; j++) {
            int g = j * 256 + tid;
            int row = g >> 3, c = g & 7;
            int e = e0 + (row & 127);
            int idx = 0;
            if (e < E)
                idx = ei64 ? (int)((const long long*)idxb)[row]
                           : ((const int*)idxb)[row];
            cpa16(rb + row * 128 + ((c ^ (row & 7)) * 16),
                  (const char*)g_nproj_h + (size_t)idx * 128 + c * 16);
        }
    };

    int tile = blockIdx.x;
    if (tile >= ntiles) return;
    const int stride = gridDim.x;

    copy_idx(tile, 0);
    CP_COMMIT();
    CP_WAIT0();
    __syncthreads();
    gather_raw(tile, 0, 0);
    { int t1 = tile + stride; if (t1 < ntiles) copy_idx(t1, 1); }
    CP_COMMIT();

    for (int i = 0; tile < ntiles; tile += stride, i++) {
        CP_WAIT0();
        __syncthreads();

        {
            int t1 = tile + stride;
            int t2 = tile + 2 * stride;
            if (t1 < ntiles) gather_raw(t1, (i + 1) & 1, (i + 1) & 1);
            if (t2 < ntiles) copy_idx(t2, i & 1);
            CP_COMMIT();
        }

        const char* rbase = RAW + (i & 1) * RAW_BUF_B;
        int e0 = tile * EDGE_TILE;

        int e1 = e0 + wid * 16 + gid;
        int e2 = e1 + 8;
        float2 gv0 = make_float2(0.f, 0.f), gv1 = make_float2(0.f, 0.f);
        if (e1 < E) gv0 = *(const float2*)&e_geo[(size_t)e1 * GEO_DIM + tg * 2];
        if (e2 < E) gv1 = *(const float2*)&e_geo[(size_t)e2 * GEO_DIM + tg * 2];

        float acc[8][4];
        #pragma unroll
        for (int nj = 0; nj < 8; nj++)
            #pragma unroll
            for (int q = 0; q < 4; q++) acc[nj][q] = 0.f;

        #pragma unroll
        for (int ks = 0; ks < 4; ks++) {
            int co0 = ((2 * ks) ^ gid) * 16;
            int co1 = ((2 * ks + 1) ^ gid) * 16;
            __half2 s0 = *(const __half2*)(rbase + roff_s  + co0);
            __half2 s1 = *(const __half2*)(rbase + roff_s8 + co0);
            __half2 s2 = *(const __half2*)(rbase + roff_s  + co1);
            __half2 s3 = *(const __half2*)(rbase + roff_s8 + co1);
            __half2 d0 = *(const __half2*)(rbase + roff_d  + co0);
            __half2 d1 = *(const __half2*)(rbase + roff_d8 + co0);
            __half2 d2 = *(const __half2*)(rbase + roff_d  + co1);
            __half2 d3 = *(const __half2*)(rbase + roff_d8 + co1);
            __half2 p0 = __hmul2(s0, d0);
            __half2 p1 = __hmul2(s1, d1);
            __half2 p2 = __hmul2(s2, d2);
            __half2 p3 = __hmul2(s3, d3);
            unsigned a0 = *(unsigned*)&p0;
            unsigned a1 = *(unsigned*)&p1;
            unsigned a2 = *(unsigned*)&p2;
            unsigned a3 = *(unsigned*)&p3;
            #pragma unroll
            for (int nj = 0; nj < 8; nj++) {
                unsigned bb0, bb1;
                if (ks < 2) {
                    bb0 = bfr[nj][ks * 2];
                    bb1 = bfr[nj][ks * 2 + 1];
                } else {
                    const __half* wr = Wt + (nj * 8 + gid) * WT_STRIDE + ks * 16;
                    bb0 = *(const unsigned*)&wr[tg * 2];
                    bb1 = *(const unsigned*)&wr[8 + tg * 2];
                }
                asm volatile(
                    "mma.sync.aligned.m16n8k16.row.col.f32.f16.f16.f32 "
                    "{%0,%1,%2,%3}, {%4,%5,%6,%7}, {%8,%9}, {%0,%1,%2,%3};\n"
                    : "+f"(acc[nj][0]), "+f"(acc[nj][1]),
                      "+f"(acc[nj][2]), "+f"(acc[nj][3])
                    : "r"(a0), "r"(a1), "r"(a2), "r"(a3),
                      "r"(bb0), "r"(bb1));
            }
        }
        {
            __half2 h0 = __floats2half2_rn(gv0.x, gv0.y);
            __half2 h1 = __floats2half2_rn(gv1.x, gv1.y);
            unsigned ag0 = *(unsigned*)&h0;
            unsigned ag1 = *(unsigned*)&h1;
            #pragma unroll
            for (int nj = 0; nj < 8; nj++) {
                asm volatile(
                    "mma.sync.aligned.m16n8k8.row.col.f32.f16.f16.f32 "
                    "{%0,%1,%2,%3}, {%4,%5}, {%6}, {%0,%1,%2,%3};\n"
                    : "+f"(acc[nj][0]), "+f"(acc[nj][1]),
                      "+f"(acc[nj][2]), "+f"(acc[nj][3])
                    : "r"(ag0), "r"(ag1), "r"(b8[nj]));
            }
        }

        // FiLM in place
        #pragma unroll
        for (int h = 0; h < 2; h++) {
            int e = e0 + wid * 16 + gid + h * 8;
            if (e < E) {
                int bb = bid64 ? (int)((const long long*)bids)[e]
                               : ((const int*)bids)[e];
                const __half* gb = GBs + bb * GB_STRIDE;
                #pragma unroll
                for (int nj = 0; nj < 8; nj++) {
                    int col = nj * 8 + tg * 2;
                    float2 ga = __half22float2(*(const __half2*)&gb[col]);
                    float2 be = __half22float2(*(const __half2*)&gb[64 + col]);
                    float x0 = acc[nj][h * 2 + 0] + cb[nj].x;
                    float x1 = acc[nj][h * 2 + 1] + cb[nj].y;
                    acc[nj][h * 2 + 0] = fmaxf(fmaf(x0, ga.x, be.x), 0.f);
                    acc[nj][h * 2 + 1] = fmaxf(fmaf(x1, ga.y, be.y), 0.f);
                }
            }
        }

        // epilogue staged through dead RAW buffer (all frag reads done)
        __syncthreads();
        float* SOUT = (float*)(RAW + (i & 1) * RAW_BUF_B);
        #pragma unroll
        for (int pass = 0; pass < 2; pass++) {
            if ((wid >> 2) == pass) {
                int wl = wid & 3;
                #pragma unroll
                for (int h = 0; h < 2; h++) {
                    int r = wl * 16 + gid + h * 8;       // local row 0..63
                    #pragma unroll
                    for (int nj = 0; nj < 8; nj++) {
                        float2 v;
                        v.x = acc[nj][h * 2 + 0];
                        v.y = acc[nj][h * 2 + 1];
                        *(float2*)&SOUT[r * SOUT_STRIDE + nj * 8 + tg * 2] = v;
                    }
                }
            }
            __syncthreads();
            int rb0 = pass * 64;
            #pragma unroll
            for (int it = 0; it < 4; it++) {
                int flat = it * 4096 + tid * 16;         // byte in 16KB half
                int r = flat >> 8;
                int cB = flat & 255;
                int e = e0 + rb0 + r;
                if (e < E) {
                    float4 v = *(const float4*)((const char*)SOUT +
                                                r * (SOUT_STRIDE * 4) + cB);
                    *(float4*)((char*)out + (size_t)e * 256 + cB) = v;
                }
            }
            __syncthreads();
        }
    }
}

// ---------------------------------------------------------------------------
extern "C" void kernel_launch(void* const* d_in, const int* in_sizes, int n_in,
                              void* d_out, int out_size) {
    const float* nf   = (const float*)d_in[0];
    const void*  ei   = d_in[1];
    const float* eg   = (const float*)d_in[2];
    const float* cond = (const float*)d_in[3];
    const void*  bids = d_in[4];
    const float* Wn   = (const float*)d_in[5];
    const float* bn   = (const float*)d_in[6];
    const float* Wg   = (const float*)d_in[7];
    const float* bg   = (const float*)d_in[8];
    const float* Wc   = (const float*)d_in[9];
    const float* bc   = (const float*)d_in[10];
    const float* Wx   = (const float*)d_in[11];
    float* out = (float*)d_out;

    int N = in_sizes[0] / NODE_DIM;
    int E = in_sizes[2] / GEO_DIM;
    int B = in_sizes[3] / COND_DIM;
    int ntiles = (E + EDGE_TILE - 1) / EDGE_TILE;
    int npb = (N + 127) / 128;

    static int smem_set = 0;
    if (!smem_set) {
        cudaFuncSetAttribute(edge_kernel,
                             cudaFuncAttributeMaxDynamicSharedMemorySize,
                             SM_TOTAL);
        smem_set = 1;
    }

    fused_kernel<<<npb + B + WCOMB_BLOCKS + 1, 256>>>(nf, Wn, bn, cond, Wc, bc,
                                                      Wg, bg, Wx, ei, bids,
                                                      N, B, E, npb);
    int grid = 296;
    if (grid > ntiles) grid = ntiles;
    edge_kernel<<<grid, 256, SM_TOTAL>>>(ei, bids, eg, out, E, ntiles);
}

// round 14
// speedup vs baseline: 3.8953x; 1.0291x over previous
#include <cuda_runtime.h>
#include <cuda_fp16.h>
#include <stdint.h>

// ---------------------------------------------------------------------------
// EdgeFeat, Round 12: paired-k permutation (LDS.64 A-frags), cbias folded
// into beta', direct-store epilogue (staging removed; it measured neutral).
// nproj stored perm: pos p = ks*16+tg*4+h*2+b  holds  orig k = ks*16+tg*2+h*8+b.
// Wcomb is in NATURAL k order (A-frags now carry orig-k values).
// ---------------------------------------------------------------------------

#define NODE_DIM 64
#define EDGE_DIM 64
#define GEO_DIM  8
#define GEO_OUT  32
#define COND_DIM 512
#define KTOT     72
#define KPAD     80
#define MAX_NODES  100000
#define MAX_EDGES  800000
#define MAX_GRAPHS 64

#define EDGE_TILE 128
#define WT_STRIDE 88           // halfs
#define GB_STRIDE 132          // halfs (128 data + 4 pad)

// edge smem layout (bytes)
#define RAW_BUF_B  (256 * 128)                            // 32768
#define SM_RAW_OFF 0
#define SM_IDX_OFF (2 * RAW_BUF_B)                        // 65536
#define SM_IDX_B   2048
#define SM_W_OFF   (SM_IDX_OFF + 2 * SM_IDX_B)            // 69632
#define SM_W_B     (64 * WT_STRIDE * 2)                   // 11264
#define SM_GB_OFF  (SM_W_OFF + SM_W_B)                    // 80896
#define SM_GB_B    (64 * GB_STRIDE * 2)                   // 16896
#define SM_TOTAL   (SM_GB_OFF + SM_GB_B)                  // 97792

__device__ __half g_nproj_h[MAX_NODES * NODE_DIM];   // paired-k permuted cols
__device__ float  g_gamma_beta[MAX_GRAPHS * 2 * EDGE_DIM];
__device__ __half g_wcomb_h[KPAD * EDGE_DIM];        // [k][n], natural k order
__device__ float  g_cbias[EDGE_DIM];
__device__ int    g_ei_is64;
__device__ int    g_bid_is64;

struct __align__(8) Half4 { __half2 lo, hi; };

__device__ __forceinline__ void cpa16(void* smp, const void* g) {
    unsigned sa = (unsigned)__cvta_generic_to_shared(smp);
    asm volatile("cp.async.cg.shared.global [%0], [%1], 16;" :: "r"(sa), "l"(g) : "memory");
}
#define CP_COMMIT() asm volatile("cp.async.commit_group;" ::: "memory")
#define CP_WAIT0()  asm volatile("cp.async.wait_group 0;" ::: "memory")

#define WCOMB_BLOCKS 20
#define NW_STRIDE 72   // halfs

// ---------------------------------------------------------------------------
// Fused kernel: nproj tiles + FiLM + Wcomb/cbias + dtype detect.
// ---------------------------------------------------------------------------
__global__ __launch_bounds__(256) void fused_kernel(const float* __restrict__ nf,
                                                    const float* __restrict__ Wn,
                                                    const float* __restrict__ bn,
                                                    const float* __restrict__ cond,
                                                    const float* __restrict__ Wc,
                                                    const float* __restrict__ bc,
                                                    const float* __restrict__ Wg,
                                                    const float* __restrict__ bg,
                                                    const float* __restrict__ Wx,
                                                    const void* __restrict__ ei,
                                                    const void* __restrict__ bids,
                                                    int N, int B, int E, int npb) {
    int bx = blockIdx.x;
    int tid = threadIdx.x;

    if (bx < npb) {
        // ================= nproj tile (fp16 MMA) =================
        __shared__ __align__(16) __half As[128 * 64];
        __shared__ __align__(16) __half Ws[64 * NW_STRIDE];
        int lane = tid & 31;
        int wid = tid >> 5;
        int n0 = bx * 128;

        for (int i = tid; i < 64 * 64; i += 256) {
            int k = i >> 6, n = i & 63;
            Ws[n * NW_STRIDE + k] = __float2half_rn(Wn[k * 64 + n]);
        }
        {
            int row = tid >> 1, h = tid & 1;
            int n = n0 + row;
            #pragma unroll
            for (int j = 0; j < 4; j++) {
                int c = h * 4 + j;
                int base = row * 64 + ((c ^ (row & 7)) * 8);
                if (n < N) {
                    float4 a = *(const float4*)&nf[(size_t)n * 64 + c * 8];
                    float4 b = *(const float4*)&nf[(size_t)n * 64 + c * 8 + 4];
                    Half4 hv, hv2;
                    hv.lo  = __floats2half2_rn(a.x, a.y);
                    hv.hi  = __floats2half2_rn(a.z, a.w);
                    hv2.lo = __floats2half2_rn(b.x, b.y);
                    hv2.hi = __floats2half2_rn(b.z, b.w);
                    *(Half4*)&As[base]     = hv;
                    *(Half4*)&As[base + 4] = hv2;
                } else {
                    Half4 hv;
                    hv.lo = __float2half2_rn(0.f);
                    hv.hi = __float2half2_rn(0.f);
                    *(Half4*)&As[base]     = hv;
                    *(Half4*)&As[base + 4] = hv;
                }
            }
        }
        __syncthreads();

        int gid = lane >> 2;
        int tg = lane & 3;
        float2 bnj[8];
        #pragma unroll
        for (int nj = 0; nj < 8; nj++)
            bnj[nj] = *(const float2*)&bn[nj * 8 + tg * 2];

        float acc[8][4];
        #pragma unroll
        for (int nj = 0; nj < 8; nj++)
            #pragma unroll
            for (int q = 0; q < 4; q++) acc[nj][q] = 0.f;

        const char* rbase = (const char*)As;
        const int roff  = (wid * 16 + gid) * 128 + tg * 4;
        const int roff8 = roff + 8 * 128;

        #pragma unroll
        for (int ks = 0; ks < 4; ks++) {
            int co0 = ((2 * ks) ^ gid) * 16;
            int co1 = ((2 * ks + 1) ^ gid) * 16;
            unsigned a0 = *(const unsigned*)(rbase + roff  + co0);
            unsigned a1 = *(const unsigned*)(rbase + roff8 + co0);
            unsigned a2 = *(const unsigned*)(rbase + roff  + co1);
            unsigned a3 = *(const unsigned*)(rbase + roff8 + co1);
            #pragma unroll
            for (int nj = 0; nj < 8; nj++) {
                const __half* wr = Ws + (nj * 8 + gid) * NW_STRIDE + ks * 16;
                unsigned bb0 = *(const unsigned*)&wr[tg * 2];
                unsigned bb1 = *(const unsigned*)&wr[8 + tg * 2];
                asm volatile(
                    "mma.sync.aligned.m16n8k16.row.col.f32.f16.f16.f32 "
                    "{%0,%1,%2,%3}, {%4,%5,%6,%7}, {%8,%9}, {%0,%1,%2,%3};\n"
                    : "+f"(acc[nj][0]), "+f"(acc[nj][1]),
                      "+f"(acc[nj][2]), "+f"(acc[nj][3])
                    : "r"(a0), "r"(a1), "r"(a2), "r"(a3), "r"(bb0), "r"(bb1));
            }
        }

        // paired-k permuted store: thread (gid,tg) holds cols nj*8+tg*2+{0,1};
        // stored position group q16: halfs {hp[2q16], hp[2q16+1]} at p=q16*16+tg*4.
        #pragma unroll
        for (int h = 0; h < 2; h++) {
            int n = n0 + wid * 16 + gid + h * 8;
            if (n < N) {
                __half2 hp[8];
                #pragma unroll
                for (int nj = 0; nj < 8; nj++)
                    hp[nj] = __floats2half2_rn(acc[nj][h * 2] + bnj[nj].x,
                                               acc[nj][h * 2 + 1] + bnj[nj].y);
                #pragma unroll
                for (int q16 = 0; q16 < 4; q16++) {
                    uint2 v;
                    v.x = *(unsigned*)&hp[2 * q16];
                    v.y = *(unsigned*)&hp[2 * q16 + 1];
                    *(uint2*)&g_nproj_h[(size_t)n * 64 + q16 * 16 + tg * 4] = v;
                }
            }
        }
        return;
    }

    int pb = bx - npb;
    if (pb < B) {
        // ================= FiLM, MLP-16 =================
        __shared__ float part[2 * EDGE_DIM];
        int b = pb;
        int j = tid & 127;
        int h = tid >> 7;
        const float* crow = cond + (size_t)b * COND_DIM + h * 256;
        const float* wcol = Wc + (size_t)h * 256 * (2 * EDGE_DIM) + j;
        float accs[16];
        #pragma unroll
        for (int u = 0; u < 16; u++) accs[u] = 0.f;
        for (int k0 = 0; k0 < 256; k0 += 16) {
            #pragma unroll
            for (int u = 0; u < 16; u++)
                accs[u] = fmaf(crow[k0 + u],
                               wcol[(size_t)(k0 + u) * (2 * EDGE_DIM)],
                               accs[u]);
        }
        #pragma unroll
        for (int s = 8; s > 0; s >>= 1)
            #pragma unroll
            for (int u = 0; u < 8; u++)
                if (u < s) accs[u] += accs[u + s];
        float acc = accs[0];
        if (h == 1) part[j] = acc;
        __syncthreads();
        if (h == 0) {
            acc += part[j] + bc[j];
            if (j < EDGE_DIM) acc += 1.0f;
            g_gamma_beta[b * (2 * EDGE_DIM) + j] = acc;
        }
    } else if (pb < B + WCOMB_BLOCKS) {
        int idx = (pb - B) * 256 + tid;
        if (idx < KPAD * EDGE_DIM) {
            int k = idx >> 6, c = idx & 63;
            float v = 0.f;
            if (k < EDGE_DIM) {
                v = Wx[k * EDGE_DIM + c];               // natural order
            } else if (k < KTOT) {
                int gk = k - EDGE_DIM;
                #pragma unroll
                for (int m = 0; m < GEO_OUT; m++)
                    v += Wg[gk * GEO_OUT + m] * Wx[(EDGE_DIM + m) * EDGE_DIM + c];
            }
            g_wcomb_h[idx] = __float2half_rn(v);
        }
        if (pb == B && tid < EDGE_DIM) {
            int c = tid;
            float v = 0.f;
            #pragma unroll
            for (int m = 0; m < GEO_OUT; m++)
                v += bg[m] * Wx[(EDGE_DIM + m) * EDGE_DIM + c];
            g_cbias[c] = v;
        }
    } else {
        // dtype probe: values < 2^17; nonzero high word => int32 packing
        __shared__ int bad[2];
        if (tid == 0) { bad[0] = 0; bad[1] = 0; }
        __syncthreads();
        const unsigned long long* p64 = (const unsigned long long*)ei;
        const unsigned long long* b64 = (const unsigned long long*)bids;
        const int samples = 2048;
        long long st_e = (long long)E / samples; if (st_e < 1) st_e = 1;
        for (int i = tid; i < samples; i += blockDim.x) {
            long long idx = (long long)i * st_e;
            if (idx >= E) break;
            if (p64[idx] >> 32) bad[0] = 1;
        }
        long long n_b = E / 2;
        long long st_b = n_b / samples; if (st_b < 1) st_b = 1;
        for (int i = tid; i < samples; i += blockDim.x) {
            long long idx = (long long)i * st_b;
            if (idx >= n_b) break;
            if (b64[idx] >> 32) bad[1] = 1;
        }
        __syncthreads();
        if (tid == 0) { g_ei_is64 = !bad[0]; g_bid_is64 = !bad[1]; }
    }
}

// ---------------------------------------------------------------------------
// Edge kernel: cp.async pipeline, LDS.64 A-frags (paired-k layout),
// beta' = beta + cbias*gamma folded at staging, direct-store epilogue.
// ---------------------------------------------------------------------------
__global__ __launch_bounds__(256, 2) void edge_kernel(const void* __restrict__ ei,
                                                      const void* __restrict__ bids,
                                                      const float* __restrict__ e_geo,
                                                      float* __restrict__ out,
                                                      int E, int ntiles) {
    extern __shared__ __align__(16) char sm[];
    char*   RAW  = sm + SM_RAW_OFF;
    char*   IDX  = sm + SM_IDX_OFF;
    __half* Wt   = (__half*)(sm + SM_W_OFF);
    __half* GBs  = (__half*)(sm + SM_GB_OFF);

    const int tid = threadIdx.x;
    const int lane = tid & 31;
    const int wid = tid >> 5;
    const int ei64 = g_ei_is64;
    const int bid64 = g_bid_is64;
    const int esz = ei64 ? 8 : 4;

    for (int i = tid; i < KTOT * EDGE_DIM; i += 256) {
        int k = i / 64, n = i & 63;
        Wt[n * WT_STRIDE + k] = g_wcomb_h[k * 64 + n];
    }
    // gamma as-is; beta' = beta + cbias*gamma
    for (int i = tid; i < 64 * 2 * EDGE_DIM; i += 256) {
        int b = i >> 7, c = i & 127;
        float v = g_gamma_beta[i];
        if (c >= 64)
            v += g_cbias[c - 64] * g_gamma_beta[b * 128 + (c - 64)];
        GBs[b * GB_STRIDE + c] = __float2half_rn(v);
    }
    __syncthreads();

    const int gid = lane >> 2;
    const int tg = lane & 3;

    unsigned bfr[8][4];
    unsigned b8[8];
    #pragma unroll
    for (int nj = 0; nj < 8; nj++) {
        const __half* wr = Wt + (nj * 8 + gid) * WT_STRIDE;
        #pragma unroll
        for (int ks = 0; ks < 2; ks++) {
            bfr[nj][ks * 2 + 0] = *(const unsigned*)&wr[ks * 16 + tg * 2];
            bfr[nj][ks * 2 + 1] = *(const unsigned*)&wr[ks * 16 + 8 + tg * 2];
        }
        b8[nj] = *(const unsigned*)&wr[64 + tg * 2];
    }

    // per-thread frag base: row = wid*16+gid ; LDS.64 target offsets per ks
    const int rowS = wid * 16 + gid;

    auto copy_idx = [&](int tile, int buf) {
        int e0 = tile * EDGE_TILE;
        int nch = 8 * esz;
        int epc = 16 / esz;
        char* dst = IDX + buf * SM_IDX_B;
        if (tid < nch) {
            if (e0 + tid * epc < E)
                cpa16(dst + tid * 16, (const char*)ei + (size_t)e0 * esz + tid * 16);
        } else if (tid >= 128 && tid - 128 < nch) {
            int t = tid - 128;
            if (e0 + t * epc < E)
                cpa16(dst + nch * 16 + t * 16,
                      (const char*)ei + ((size_t)E + e0) * esz + t * 16);
        }
    };
    auto gather_raw = [&](int tile, int rbuf, int ibuf) {
        int e0 = tile * EDGE_TILE;
        char* rb = RAW + rbuf * RAW_BUF_B;
        const char* idxb = IDX + ibuf * SM_IDX_B;
        #pragma unroll
        for (int j = 0; j < 8; j++) {
            int g = j * 256 + tid;
            int row = g >> 3, c = g & 7;
            int e = e0 + (row & 127);
            int idx = 0;
            if (e < E)
                idx = ei64 ? (int)((const long long*)idxb)[row]
                           : ((const int*)idxb)[row];
            cpa16(rb + row * 128 + ((c ^ (row & 7)) * 16),
                  (const char*)g_nproj_h + (size_t)idx * 128 + c * 16);
        }
    };

    int tile = blockIdx.x;
    if (tile >= ntiles) return;
    const int stride = gridDim.x;

    copy_idx(tile, 0);
    CP_COMMIT();
    CP_WAIT0();
    __syncthreads();
    gather_raw(tile, 0, 0);
    { int t1 = tile + stride; if (t1 < ntiles) copy_idx(t1, 1); }
    CP_COMMIT();

    for (int i = 0; tile < ntiles; tile += stride, i++) {
        CP_WAIT0();
        __syncthreads();

        {
            int t1 = tile + stride;
            int t2 = tile + 2 * stride;
            if (t1 < ntiles) gather_raw(t1, (i + 1) & 1, (i + 1) & 1);
            if (t2 < ntiles) copy_idx(t2, i & 1);
            CP_COMMIT();
        }

        const char* rbase = RAW + (i & 1) * RAW_BUF_B;
        int e0 = tile * EDGE_TILE;

        int e1 = e0 + wid * 16 + gid;
        int e2 = e1 + 8;
        float2 gv0 = make_float2(0.f, 0.f), gv1 = make_float2(0.f, 0.f);
        if (e1 < E) gv0 = *(const float2*)&e_geo[(size_t)e1 * GEO_DIM + tg * 2];
        if (e2 < E) gv1 = *(const float2*)&e_geo[(size_t)e2 * GEO_DIM + tg * 2];

        float acc[8][4];
        #pragma unroll
        for (int nj = 0; nj < 8; nj++)
            #pragma unroll
            for (int q = 0; q < 4; q++) acc[nj][q] = 0.f;

        #pragma unroll
        for (int ks = 0; ks < 4; ks++) {
            int q = ks * 4 + tg;
            int off = (((q >> 1) ^ gid) * 16) + ((q & 1) * 8);
            const char* sp = rbase + rowS * 128 + off;
            uint2 s0 = *(const uint2*)(sp);
            uint2 s1 = *(const uint2*)(sp + 8 * 128);
            uint2 d0 = *(const uint2*)(sp + 128 * 128);
            uint2 d1 = *(const uint2*)(sp + 136 * 128);
            __half2 p0 = __hmul2(*(__half2*)&s0.x, *(__half2*)&d0.x);
            __half2 p2 = __hmul2(*(__half2*)&s0.y, *(__half2*)&d0.y);
            __half2 p1 = __hmul2(*(__half2*)&s1.x, *(__half2*)&d1.x);
            __half2 p3 = __hmul2(*(__half2*)&s1.y, *(__half2*)&d1.y);
            unsigned a0 = *(unsigned*)&p0;
            unsigned a1 = *(unsigned*)&p1;
            unsigned a2 = *(unsigned*)&p2;
            unsigned a3 = *(unsigned*)&p3;
            #pragma unroll
            for (int nj = 0; nj < 8; nj++) {
                unsigned bb0, bb1;
                if (ks < 2) {
                    bb0 = bfr[nj][ks * 2];
                    bb1 = bfr[nj][ks * 2 + 1];
                } else {
                    const __half* wr = Wt + (nj * 8 + gid) * WT_STRIDE + ks * 16;
                    bb0 = *(const unsigned*)&wr[tg * 2];
                    bb1 = *(const unsigned*)&wr[8 + tg * 2];
                }
                asm volatile(
                    "mma.sync.aligned.m16n8k16.row.col.f32.f16.f16.f32 "
                    "{%0,%1,%2,%3}, {%4,%5,%6,%7}, {%8,%9}, {%0,%1,%2,%3};\n"
                    : "+f"(acc[nj][0]), "+f"(acc[nj][1]),
                      "+f"(acc[nj][2]), "+f"(acc[nj][3])
                    : "r"(a0), "r"(a1), "r"(a2), "r"(a3),
                      "r"(bb0), "r"(bb1));
            }
        }
        {
            __half2 h0 = __floats2half2_rn(gv0.x, gv0.y);
            __half2 h1 = __floats2half2_rn(gv1.x, gv1.y);
            unsigned ag0 = *(unsigned*)&h0;
            unsigned ag1 = *(unsigned*)&h1;
            #pragma unroll
            for (int nj = 0; nj < 8; nj++) {
                asm volatile(
                    "mma.sync.aligned.m16n8k8.row.col.f32.f16.f16.f32 "
                    "{%0,%1,%2,%3}, {%4,%5}, {%6}, {%0,%1,%2,%3};\n"
                    : "+f"(acc[nj][0]), "+f"(acc[nj][1]),
                      "+f"(acc[nj][2]), "+f"(acc[nj][3])
                    : "r"(ag0), "r"(ag1), "r"(b8[nj]));
            }
        }

        // epilogue: FiLM (gamma, beta') + relu, direct float2 stores
        #pragma unroll
        for (int h = 0; h < 2; h++) {
            int e = e0 + wid * 16 + gid + h * 8;
            if (e < E) {
                int bb = bid64 ? (int)((const long long*)bids)[e]
                               : ((const int*)bids)[e];
                const __half* gb = GBs + bb * GB_STRIDE;
                #pragma unroll
                for (int nj = 0; nj < 8; nj++) {
                    int col = nj * 8 + tg * 2;
                    float2 ga = __half22float2(*(const __half2*)&gb[col]);
                    float2 be = __half22float2(*(const __half2*)&gb[64 + col]);
                    float2 o;
                    o.x = fmaxf(fmaf(acc[nj][h * 2 + 0], ga.x, be.x), 0.f);
                    o.y = fmaxf(fmaf(acc[nj][h * 2 + 1], ga.y, be.y), 0.f);
                    *(float2*)&out[(size_t)e * 64 + col] = o;
                }
            }
        }
    }
}

// ---------------------------------------------------------------------------
extern "C" void kernel_launch(void* const* d_in, const int* in_sizes, int n_in,
                              void* d_out, int out_size) {
    const float* nf   = (const float*)d_in[0];
    const void*  ei   = d_in[1];
    const float* eg   = (const float*)d_in[2];
    const float* cond = (const float*)d_in[3];
    const void*  bids = d_in[4];
    const float* Wn   = (const float*)d_in[5];
    const float* bn   = (const float*)d_in[6];
    const float* Wg   = (const float*)d_in[7];
    const float* bg   = (const float*)d_in[8];
    const float* Wc   = (const float*)d_in[9];
    const float* bc   = (const float*)d_in[10];
    const float* Wx   = (const float*)d_in[11];
    float* out = (float*)d_out;

    int N = in_sizes[0] / NODE_DIM;
    int E = in_sizes[2] / GEO_DIM;
    int B = in_sizes[3] / COND_DIM;
    int ntiles = (E + EDGE_TILE - 1) / EDGE_TILE;
    int npb = (N + 127) / 128;

    static int smem_set = 0;
    if (!smem_set) {
        cudaFuncSetAttribute(edge_kernel,
                             cudaFuncAttributeMaxDynamicSharedMemorySize,
                             SM_TOTAL);
        smem_set = 1;
    }

    fused_kernel<<<npb + B + WCOMB_BLOCKS + 1, 256>>>(nf, Wn, bn, cond, Wc, bc,
                                                      Wg, bg, Wx, ei, bids,
                                                      N, B, E, npb);
    int grid = 296;
    if (grid > ntiles) grid = ntiles;
    edge_kernel<<<grid, 256, SM_TOTAL>>>(ei, bids, eg, out, E, ntiles);
}